// round 10
// baseline (speedup 1.0000x reference)
#include <cuda_runtime.h>
#include <cuda_bf16.h>
#include <math.h>
#include <stdint.h>

// Problem constants
#define BATCH 4
#define SEQ   2048
#define DMODEL 768
#define NHEAD 12
#define DHEAD 64
#define DFF   3072
#define MROWS (BATCH*SEQ)          // 8192
#define EPS   1e-5f

// ---------------------------------------------------------------------------
// Scratch (device globals; allocation-free contract)
// ---------------------------------------------------------------------------
__device__ float g_q  [(size_t)MROWS * DMODEL];   // tf32, pre-scaled 1/8
__device__ float g_k  [(size_t)MROWS * DMODEL];   // tf32
__device__ float g_v  [(size_t)MROWS * DMODEL];   // tf32
__device__ float g_ctx[(size_t)MROWS * DMODEL];   // tf32 (attn epilogue rounds)
__device__ float g_t1 [(size_t)MROWS * DMODEL];
__device__ float g_h  [(size_t)MROWS * DMODEL];   // full fp32 (residual)
__device__ float g_hr [(size_t)MROWS * DMODEL];   // tf32 (FFN1 A operand)
__device__ float g_f1 [(size_t)MROWS * DFF];      // tf32 (GELU epilogue rounds)
__device__ float g_t2 [(size_t)MROWS * DMODEL];
// pre-rounded activations + pre-rounded TRANSPOSED weights [N][K]
__device__ float g_xr [(size_t)MROWS * DMODEL];
__device__ float g_wqT[(size_t)DMODEL * DMODEL];
__device__ float g_wkT[(size_t)DMODEL * DMODEL];
__device__ float g_wvT[(size_t)DMODEL * DMODEL];
__device__ float g_woT[(size_t)DMODEL * DMODEL];
__device__ float g_w1T[(size_t)DFF * DMODEL];     // [3072][768]
__device__ float g_w2T[(size_t)DMODEL * DFF];     // [768][3072]

// ---------------------------------------------------------------------------
// tf32 helpers
// ---------------------------------------------------------------------------
__device__ __forceinline__ float f2tf32(float x)
{
    uint32_t u;
    asm("cvt.rna.tf32.f32 %0, %1;" : "=r"(u) : "f"(x));
    return __uint_as_float(u);
}

__device__ __forceinline__ void mma_tf32(float* c, const uint32_t* a, const uint32_t* b)
{
    asm volatile(
        "mma.sync.aligned.m16n8k8.row.col.f32.tf32.tf32.f32 "
        "{%0,%1,%2,%3},{%4,%5,%6,%7},{%8,%9},{%0,%1,%2,%3};\n"
        : "+f"(c[0]), "+f"(c[1]), "+f"(c[2]), "+f"(c[3])
        : "r"(a[0]), "r"(a[1]), "r"(a[2]), "r"(a[3]), "r"(b[0]), "r"(b[1]));
}

__device__ __forceinline__ uint32_t smem_u32(const void* p)
{
    return (uint32_t)__cvta_generic_to_shared(p);
}

#define LDSM4(r0, r1, r2, r3, addr)                                          \
    asm volatile("ldmatrix.sync.aligned.m8n8.x4.shared.b16 {%0,%1,%2,%3}, [%4];" \
                 : "=r"(r0), "=r"(r1), "=r"(r2), "=r"(r3) : "r"(addr))

#define CPA16(dst, src) \
    asm volatile("cp.async.cg.shared.global [%0], [%1], 16;\n" :: "r"(dst), "l"(src))
#define CPA_COMMIT() asm volatile("cp.async.commit_group;\n")
#define CPA_WAIT1()  asm volatile("cp.async.wait_group 1;\n")
#define CPA_WAIT0()  asm volatile("cp.async.wait_group 0;\n")

// ---------------------------------------------------------------------------
// Prep kernels: tf32 rounding (activations) and round+transpose (weights)
// ---------------------------------------------------------------------------
__global__ __launch_bounds__(256)
void round_tf32_kernel(const float* __restrict__ src, float* __restrict__ dst, int n4)
{
    const int i = blockIdx.x * blockDim.x + threadIdx.x;
    if (i < n4) {
        float4 v = *((const float4*)src + i);
        v.x = f2tf32(v.x); v.y = f2tf32(v.y);
        v.z = f2tf32(v.z); v.w = f2tf32(v.w);
        *((float4*)dst + i) = v;
    }
}

// src [K][N] row-major -> dst [N][K] row-major, tf32-rounded.
__global__ __launch_bounds__(256)
void roundT_kernel(const float* __restrict__ src, float* __restrict__ dst,
                   int K, int N)
{
    __shared__ float t[32][33];
    const int k0 = blockIdx.x * 32;
    const int n0 = blockIdx.y * 32;
    const int x = threadIdx.x;       // 0..31
    const int y = threadIdx.y;       // 0..7
    #pragma unroll
    for (int i = 0; i < 32; i += 8)
        t[y + i][x] = src[(size_t)(k0 + y + i) * N + n0 + x];
    __syncthreads();
    #pragma unroll
    for (int i = 0; i < 32; i += 8)
        dst[(size_t)(n0 + y + i) * K + k0 + x] = f2tf32(t[x][y + i]);
}

// ---------------------------------------------------------------------------
// cp.async tf32 GEMM with ldmatrix fragment loads.
// C[M,N] = A[M,K] @ BT[N,K]^T + bias (+resid / GELU->tf32 / tf32).
// A and BT MUST be pre-rounded tf32 in gmem; BT is [N][K].
// BM=128 BN=128 BK=16, 256 threads (8 warps 2x4, warp tile 64x32).
// 3-stage cp.async pipeline. A and B smem both [row][k] pitch 20
// (ldmatrix phases hit all 32 banks).
// ---------------------------------------------------------------------------
enum { EP_RESID = 1, EP_GELU_TF32 = 2, EP_TF32 = 3 };

#define APITCH 20
#define ABUF   (128*APITCH)   // 2560 floats
#define BPITCH 20
#define BBUF   (128*BPITCH)   // 2560 floats
#define GEMM_SMEM ((3*ABUF + 3*BBUF) * 4)   // 61440 B

template<int EPI>
__global__ __launch_bounds__(256)
void gemm_ca(const float* __restrict__ A, const float* __restrict__ BT,
             const float* __restrict__ bias, const float* __restrict__ resid,
             float* __restrict__ C, int Ndim, int Kdim, float oscale)
{
    extern __shared__ float gsm[];
    float* As = gsm;             // [3][128][APITCH]  (m rows)
    float* Bs = gsm + 3*ABUF;    // [3][128][BPITCH]  (n rows)

    const int tid  = threadIdx.x;
    const int lane = tid & 31;
    const int warp = tid >> 5;
    const int wm = warp & 1;
    const int wn = warp >> 1;
    const int g = lane >> 2;
    const int q = lane & 3;
    const int row0 = blockIdx.y * 128;
    const int col0 = blockIdx.x * 128;

    // cp.async mapping: 2 threads per row, 8 floats each (A and B identical)
    const int ar  = tid >> 1;           // 0..127
    const int ac8 = (tid & 1) * 8;      // 0 or 8

    const uint32_t asu = smem_u32(As);
    const uint32_t bsu = smem_u32(Bs);

    // ldmatrix per-lane offsets (bytes, within a buffer)
    const int lrow = lane & 15;
    const int lhi  = (lane >> 4) * 4;   // k offset 0 or 4
    const uint32_t aoff = (uint32_t)((wm*64 + lrow) * APITCH + lhi) * 4u;
    const uint32_t boff = (uint32_t)((wn*32 + lrow) * BPITCH + lhi) * 4u;

    float acc[4][4][4];
    #pragma unroll
    for (int i = 0; i < 4; i++)
        #pragma unroll
        for (int j = 0; j < 4; j++)
            #pragma unroll
            for (int r = 0; r < 4; r++) acc[i][j][r] = 0.f;

    const int nk = Kdim >> 4;

    #define GISSUE(i, bf_) do {                                                   \
        const int k0_ = (i) << 4;                                                 \
        const float* asrc = A  + (size_t)(row0 + ar) * Kdim + k0_ + ac8;          \
        const uint32_t ad = asu + (uint32_t)((bf_)*ABUF + ar*APITCH + ac8) * 4u;  \
        CPA16(ad,       asrc);                                                    \
        CPA16(ad + 16u, asrc + 4);                                                \
        const float* bsrc = BT + (size_t)(col0 + ar) * Kdim + k0_ + ac8;          \
        const uint32_t bd = bsu + (uint32_t)((bf_)*BBUF + ar*BPITCH + ac8) * 4u;  \
        CPA16(bd,       bsrc);                                                    \
        CPA16(bd + 16u, bsrc + 4);                                                \
        CPA_COMMIT();                                                             \
    } while (0)

    #define GCOMPUTE(bf_) do {                                                    \
        const uint32_t abase = asu + (uint32_t)((bf_)*ABUF) * 4u + aoff;          \
        const uint32_t bbase = bsu + (uint32_t)((bf_)*BBUF) * 4u + boff;          \
        _Pragma("unroll")                                                         \
        for (int ks = 0; ks < 16; ks += 8) {                                      \
            uint32_t af[4][4], bf2[4][2];                                         \
            _Pragma("unroll")                                                     \
            for (int mt = 0; mt < 4; mt++)                                        \
                LDSM4(af[mt][0], af[mt][1], af[mt][2], af[mt][3],                 \
                      abase + (uint32_t)(mt*16*APITCH + ks) * 4u);                \
            _Pragma("unroll")                                                     \
            for (int ntp = 0; ntp < 2; ntp++)                                     \
                LDSM4(bf2[2*ntp][0], bf2[2*ntp+1][0],                             \
                      bf2[2*ntp][1], bf2[2*ntp+1][1],                             \
                      bbase + (uint32_t)(ntp*16*BPITCH + ks) * 4u);               \
            _Pragma("unroll")                                                     \
            for (int mt = 0; mt < 4; mt++)                                        \
                _Pragma("unroll")                                                 \
                for (int nt = 0; nt < 4; nt++)                                    \
                    mma_tf32(acc[mt][nt], af[mt], bf2[nt]);                       \
        }                                                                         \
    } while (0)

    GISSUE(0, 0);
    GISSUE(1, 1);

    for (int i = 0; i < nk; i++) {
        if (i + 1 < nk) { CPA_WAIT1(); } else { CPA_WAIT0(); }
        __syncthreads();
        const int cb = i % 3;
        GCOMPUTE(cb);
        if (i + 2 < nk) GISSUE(i + 2, (i + 2) % 3);
        __syncthreads();    // all warps done reading buf cb before it is reused
    }

    #undef GISSUE
    #undef GCOMPUTE

    // epilogue
    #pragma unroll
    for (int mt = 0; mt < 4; mt++) {
        const int mlo = row0 + wm*64 + mt*16 + g;
        #pragma unroll
        for (int nt = 0; nt < 4; nt++) {
            const int n = col0 + wn*32 + nt*8 + 2*q;
            const float b0 = bias[n], b1 = bias[n+1];
            #pragma unroll
            for (int half = 0; half < 2; half++) {
                const int m = mlo + half*8;
                float v0 = acc[mt][nt][half*2+0] + b0;
                float v1 = acc[mt][nt][half*2+1] + b1;
                if (EPI == EP_RESID) {
                    v0 += resid[(size_t)m * Ndim + n];
                    v1 += resid[(size_t)m * Ndim + n + 1];
                }
                if (EPI == EP_GELU_TF32) {
                    v0 = f2tf32(0.5f * v0 * (1.0f + erff(v0 * 0.70710678118654752f)));
                    v1 = f2tf32(0.5f * v1 * (1.0f + erff(v1 * 0.70710678118654752f)));
                }
                if (EPI == EP_TF32) {
                    v0 = f2tf32(v0 * oscale);
                    v1 = f2tf32(v1 * oscale);
                }
                *(float2*)(C + (size_t)m * Ndim + n) = make_float2(v0, v1);
            }
        }
    }
}

// ---------------------------------------------------------------------------
// Tensor-core flash attention (causal, tf32 mma). UNCHANGED from R9.
// CTA = 8 warps = 128 query rows of one (b,h). 64-key tiles, cp.async x2 buf.
// ---------------------------------------------------------------------------
#define PK 68
#define PV 72
#define PP 68
#define ATTN_SMEM ((2*64*PK + 2*64*PV + 128*PP) * 4)

__global__ __launch_bounds__(256, 2)
void attn_tc(const float* __restrict__ Q, const float* __restrict__ K,
             const float* __restrict__ V, float* __restrict__ ctx)
{
    extern __shared__ float sm[];
    float* Kb[2] = { sm, sm + 64*PK };
    float* Vb[2] = { sm + 2*64*PK, sm + 2*64*PK + 64*PV };
    float* Ps    = sm + 2*64*PK + 2*64*PV;      // [128][PP], also Q staging

    const int bh = blockIdx.y;
    const int b  = bh / NHEAD;
    const int h  = bh % NHEAD;
    const int qt = (SEQ/128 - 1) - blockIdx.x;  // heavy CTAs first
    const int tid  = threadIdx.x;
    const int warp = tid >> 5;
    const int lane = tid & 31;
    const int g = lane >> 2;
    const int q = lane & 3;
    const int wrow = warp * 16;                 // 0..112
    const int qbase = qt * 128;

    const int lr = tid >> 2;                    // 0..63
    const int cb = (tid & 3) * 4;               // float4 chunk base

    const uint32_t kbu[2] = { smem_u32(Kb[0]), smem_u32(Kb[1]) };
    const uint32_t vbu[2] = { smem_u32(Vb[0]), smem_u32(Vb[1]) };

    #define ISSUE_TILE(kb, sel) do {                                                 \
        const float* kbase = K + ((size_t)(b*SEQ + (kb)*64 + lr))*DMODEL + h*DHEAD;  \
        const float* vbase = V + ((size_t)(b*SEQ + (kb)*64 + lr))*DMODEL + h*DHEAD;  \
        const uint32_t kd = kbu[sel] + (uint32_t)(lr*PK)*4u + (uint32_t)cb*16u;      \
        const uint32_t vd = vbu[sel] + (uint32_t)(lr*PV)*4u + (uint32_t)cb*16u;      \
        _Pragma("unroll")                                                            \
        for (int i = 0; i < 4; i++) {                                                \
            CPA16(kd + i*16u, kbase + (cb + i)*4);                                   \
            CPA16(vd + i*16u, vbase + (cb + i)*4);                                   \
        }                                                                            \
        CPA_COMMIT();                                                                \
    } while (0)

    ISSUE_TILE(0, 0);

    // ---- stage Q (128 rows) through Ps, read fragments into registers ----
    {
        const int qlr = tid >> 1;
        const int qlc = (tid & 1) * 8;
        const float* qsrc = Q + ((size_t)(b*SEQ + qbase + qlr))*DMODEL + h*DHEAD;
        #pragma unroll
        for (int i = 0; i < 8; i++)
            *(float4*)&Ps[qlr*PP + (qlc + i)*4] = *(const float4*)(qsrc + (qlc + i)*4);
    }
    __syncthreads();
    uint32_t qf[8][4];
    #pragma unroll
    for (int ks8 = 0; ks8 < 8; ks8++) {
        qf[ks8][0] = __float_as_uint(Ps[(wrow+g  )*PP + ks8*8 + q  ]);
        qf[ks8][1] = __float_as_uint(Ps[(wrow+g+8)*PP + ks8*8 + q  ]);
        qf[ks8][2] = __float_as_uint(Ps[(wrow+g  )*PP + ks8*8 + q+4]);
        qf[ks8][3] = __float_as_uint(Ps[(wrow+g+8)*PP + ks8*8 + q+4]);
    }
    __syncthreads();

    float oacc[8][4];
    #pragma unroll
    for (int nt = 0; nt < 8; nt++)
        #pragma unroll
        for (int e = 0; e < 4; e++) oacc[nt][e] = 0.f;
    float m0 = -1e30f, m1 = -1e30f, l0 = 0.f, l1 = 0.f;

    const int nkb = 2*qt + 2;

    for (int kb = 0; kb < nkb; kb++) {
        const int cur = kb & 1;
        if (kb + 1 < nkb) {
            ISSUE_TILE(kb + 1, cur ^ 1);
            CPA_WAIT1();
        } else {
            CPA_WAIT0();
        }
        __syncthreads();

        const bool skip = (kb*64) > (qbase + wrow + 15);
        if (!skip) {
            const float* Ksm = Kb[cur];
            const float* Vsm = Vb[cur];

            float sacc[8][4];
            #pragma unroll
            for (int nt = 0; nt < 8; nt++)
                #pragma unroll
                for (int e = 0; e < 4; e++) sacc[nt][e] = 0.f;

            #pragma unroll
            for (int ks8 = 0; ks8 < 8; ks8++) {
                const int ks = ks8 * 8;
                #pragma unroll
                for (int nt = 0; nt < 8; nt++) {
                    uint32_t bb[2];
                    bb[0] = __float_as_uint(Ksm[(nt*8+g)*PK + ks+q  ]);
                    bb[1] = __float_as_uint(Ksm[(nt*8+g)*PK + ks+q+4]);
                    mma_tf32(sacc[nt], qf[ks8], bb);
                }
            }

            if (kb*64 + 63 > qbase + wrow) {
                const int r0 = qbase + wrow + g;
                const int r1 = r0 + 8;
                #pragma unroll
                for (int nt = 0; nt < 8; nt++) {
                    const int colg = kb*64 + nt*8 + 2*q;
                    if (colg     > r0) sacc[nt][0] = -1e30f;
                    if (colg + 1 > r0) sacc[nt][1] = -1e30f;
                    if (colg     > r1) sacc[nt][2] = -1e30f;
                    if (colg + 1 > r1) sacc[nt][3] = -1e30f;
                }
            }

            float rm0 = -1e30f, rm1 = -1e30f;
            #pragma unroll
            for (int nt = 0; nt < 8; nt++) {
                rm0 = fmaxf(rm0, fmaxf(sacc[nt][0], sacc[nt][1]));
                rm1 = fmaxf(rm1, fmaxf(sacc[nt][2], sacc[nt][3]));
            }
            rm0 = fmaxf(rm0, __shfl_xor_sync(0xffffffffu, rm0, 1));
            rm0 = fmaxf(rm0, __shfl_xor_sync(0xffffffffu, rm0, 2));
            rm1 = fmaxf(rm1, __shfl_xor_sync(0xffffffffu, rm1, 1));
            rm1 = fmaxf(rm1, __shfl_xor_sync(0xffffffffu, rm1, 2));

            const float mn0 = fmaxf(m0, rm0);
            const float mn1 = fmaxf(m1, rm1);
            const float c0 = __expf(m0 - mn0);
            const float c1 = __expf(m1 - mn1);
            m0 = mn0; m1 = mn1;

            float s0 = 0.f, s1 = 0.f;
            #pragma unroll
            for (int nt = 0; nt < 8; nt++) {
                float p;
                p = __expf(sacc[nt][0] - mn0); s0 += p; sacc[nt][0] = p;
                p = __expf(sacc[nt][1] - mn0); s0 += p; sacc[nt][1] = p;
                p = __expf(sacc[nt][2] - mn1); s1 += p; sacc[nt][2] = p;
                p = __expf(sacc[nt][3] - mn1); s1 += p; sacc[nt][3] = p;
            }
            s0 += __shfl_xor_sync(0xffffffffu, s0, 1);
            s0 += __shfl_xor_sync(0xffffffffu, s0, 2);
            s1 += __shfl_xor_sync(0xffffffffu, s1, 1);
            s1 += __shfl_xor_sync(0xffffffffu, s1, 2);
            l0 = l0 * c0 + s0;
            l1 = l1 * c1 + s1;

            #pragma unroll
            for (int nt = 0; nt < 8; nt++) {
                oacc[nt][0] *= c0; oacc[nt][1] *= c0;
                oacc[nt][2] *= c1; oacc[nt][3] *= c1;
            }

            #pragma unroll
            for (int nt = 0; nt < 8; nt++) {
                *(float2*)&Ps[(wrow+g  )*PP + nt*8 + 2*q] =
                    make_float2(f2tf32(sacc[nt][0]), f2tf32(sacc[nt][1]));
                *(float2*)&Ps[(wrow+g+8)*PP + nt*8 + 2*q] =
                    make_float2(f2tf32(sacc[nt][2]), f2tf32(sacc[nt][3]));
            }
            __syncwarp();

            #pragma unroll
            for (int ks8 = 0; ks8 < 8; ks8++) {
                const int ks = ks8 * 8;
                uint32_t a[4];
                a[0] = __float_as_uint(Ps[(wrow+g  )*PP + ks+q  ]);
                a[1] = __float_as_uint(Ps[(wrow+g+8)*PP + ks+q  ]);
                a[2] = __float_as_uint(Ps[(wrow+g  )*PP + ks+q+4]);
                a[3] = __float_as_uint(Ps[(wrow+g+8)*PP + ks+q+4]);
                #pragma unroll
                for (int nt = 0; nt < 8; nt++) {
                    uint32_t bb[2];
                    bb[0] = __float_as_uint(Vsm[(ks+q  )*PV + nt*8+g]);
                    bb[1] = __float_as_uint(Vsm[(ks+q+4)*PV + nt*8+g]);
                    mma_tf32(oacc[nt], a, bb);
                }
            }
        }
        __syncthreads();
    }
    #undef ISSUE_TILE

    const float i0 = 1.f / l0;
    const float i1 = 1.f / l1;
    float* c0p = ctx + ((size_t)(b*SEQ + qbase + wrow + g    )) * DMODEL + h*DHEAD;
    float* c1p = ctx + ((size_t)(b*SEQ + qbase + wrow + g + 8)) * DMODEL + h*DHEAD;
    #pragma unroll
    for (int nt = 0; nt < 8; nt++) {
        *(float2*)(c0p + nt*8 + 2*q) =
            make_float2(f2tf32(oacc[nt][0]*i0), f2tf32(oacc[nt][1]*i0));
        *(float2*)(c1p + nt*8 + 2*q) =
            make_float2(f2tf32(oacc[nt][2]*i1), f2tf32(oacc[nt][3]*i1));
    }
}

// ---------------------------------------------------------------------------
// Row-wise LayerNorm over 768 elems. 256 threads/row.
// ---------------------------------------------------------------------------
__global__ __launch_bounds__(256)
void ln_kernel(const float* __restrict__ X, const float* __restrict__ g,
               const float* __restrict__ be, float* __restrict__ Y,
               float* __restrict__ Yr)
{
    __shared__ float red[8];
    const int row = blockIdx.x;
    const int tid = threadIdx.x;
    const float* x = X + (size_t)row * DMODEL;

    float v[3];
    float s = 0.f;
    #pragma unroll
    for (int i = 0; i < 3; i++) { v[i] = x[tid + i * 256]; s += v[i]; }

    #pragma unroll
    for (int off = 16; off; off >>= 1) s += __shfl_xor_sync(0xffffffffu, s, off);
    if ((tid & 31) == 0) red[tid >> 5] = s;
    __syncthreads();
    float total = 0.f;
    #pragma unroll
    for (int i = 0; i < 8; i++) total += red[i];
    const float mean = total * (1.0f / DMODEL);
    __syncthreads();

    float s2 = 0.f;
    #pragma unroll
    for (int i = 0; i < 3; i++) { const float d = v[i] - mean; s2 += d * d; }
    #pragma unroll
    for (int off = 16; off; off >>= 1) s2 += __shfl_xor_sync(0xffffffffu, s2, off);
    if ((tid & 31) == 0) red[tid >> 5] = s2;
    __syncthreads();
    float tot2 = 0.f;
    #pragma unroll
    for (int i = 0; i < 8; i++) tot2 += red[i];
    const float rstd = rsqrtf(tot2 * (1.0f / DMODEL) + EPS);

    #pragma unroll
    for (int i = 0; i < 3; i++) {
        const int c = tid + i * 256;
        const float y = (v[i] - mean) * rstd * g[c] + be[c];
        Y[(size_t)row * DMODEL + c] = y;
        if (Yr) Yr[(size_t)row * DMODEL + c] = f2tf32(y);
    }
}

// ---------------------------------------------------------------------------
// Launch
// ---------------------------------------------------------------------------
static float* sym_addr(const void* sym)
{
    void* p = nullptr;
    cudaGetSymbolAddress(&p, sym);
    return (float*)p;
}

extern "C" void kernel_launch(void* const* d_in, const int* in_sizes, int n_in,
                              void* d_out, int out_size)
{
    const float* x   = (const float*)d_in[0];
    // d_in[1] = mask (causal; implied)
    const float* wq  = (const float*)d_in[2];
    const float* bq  = (const float*)d_in[3];
    const float* wk  = (const float*)d_in[4];
    const float* bk  = (const float*)d_in[5];
    const float* wv  = (const float*)d_in[6];
    const float* bv  = (const float*)d_in[7];
    const float* wo  = (const float*)d_in[8];
    const float* bo  = (const float*)d_in[9];
    const float* g1  = (const float*)d_in[10];
    const float* be1 = (const float*)d_in[11];
    const float* w1  = (const float*)d_in[12];
    const float* b1  = (const float*)d_in[13];
    const float* w2  = (const float*)d_in[14];
    const float* b2  = (const float*)d_in[15];
    const float* g2  = (const float*)d_in[16];
    const float* be2 = (const float*)d_in[17];
    float* out = (float*)d_out;

    float* q   = sym_addr(g_q);
    float* k   = sym_addr(g_k);
    float* v   = sym_addr(g_v);
    float* ctx = sym_addr(g_ctx);
    float* t1  = sym_addr(g_t1);
    float* hh  = sym_addr(g_h);
    float* hr  = sym_addr(g_hr);
    float* f1  = sym_addr(g_f1);
    float* t2  = sym_addr(g_t2);
    float* xr  = sym_addr(g_xr);
    float* wqT = sym_addr(g_wqT);
    float* wkT = sym_addr(g_wkT);
    float* wvT = sym_addr(g_wvT);
    float* woT = sym_addr(g_woT);
    float* w1T = sym_addr(g_w1T);
    float* w2T = sym_addr(g_w2T);

    cudaFuncSetAttribute(attn_tc, cudaFuncAttributeMaxDynamicSharedMemorySize,
                         ATTN_SMEM);
    cudaFuncSetAttribute(gemm_ca<EP_TF32>,
                         cudaFuncAttributeMaxDynamicSharedMemorySize, GEMM_SMEM);
    cudaFuncSetAttribute(gemm_ca<EP_RESID>,
                         cudaFuncAttributeMaxDynamicSharedMemorySize, GEMM_SMEM);
    cudaFuncSetAttribute(gemm_ca<EP_GELU_TF32>,
                         cudaFuncAttributeMaxDynamicSharedMemorySize, GEMM_SMEM);

    // 0. prep: round x; round+transpose weights to [N][K]
    const int nX = MROWS * DMODEL / 4;
    round_tf32_kernel<<<(nX + 255)/256, 256>>>(x, xr, nX);
    const dim3 tb(32, 8);
    roundT_kernel<<<dim3(DMODEL/32, DMODEL/32), tb>>>(wq, wqT, DMODEL, DMODEL);
    roundT_kernel<<<dim3(DMODEL/32, DMODEL/32), tb>>>(wk, wkT, DMODEL, DMODEL);
    roundT_kernel<<<dim3(DMODEL/32, DMODEL/32), tb>>>(wv, wvT, DMODEL, DMODEL);
    roundT_kernel<<<dim3(DMODEL/32, DMODEL/32), tb>>>(wo, woT, DMODEL, DMODEL);
    roundT_kernel<<<dim3(DMODEL/32, DFF/32),    tb>>>(w1, w1T, DMODEL, DFF);
    roundT_kernel<<<dim3(DFF/32, DMODEL/32),    tb>>>(w2, w2T, DFF, DMODEL);

    const dim3 gD(DMODEL/128, MROWS/128);   // 6 x 64
    const dim3 gF(DFF/128,    MROWS/128);   // 24 x 64

    // 1. QKV projections -> tf32 [B,S,H*DK] (Q pre-scaled 1/8)
    gemm_ca<EP_TF32><<<gD, 256, GEMM_SMEM>>>(xr, wqT, bq, nullptr, q, DMODEL, DMODEL, 0.125f);
    gemm_ca<EP_TF32><<<gD, 256, GEMM_SMEM>>>(xr, wkT, bk, nullptr, k, DMODEL, DMODEL, 1.0f);
    gemm_ca<EP_TF32><<<gD, 256, GEMM_SMEM>>>(xr, wvT, bv, nullptr, v, DMODEL, DMODEL, 1.0f);

    // 2. Causal flash attention -> ctx (tf32)
    attn_tc<<<dim3(SEQ/128, BATCH*NHEAD), 256, ATTN_SMEM>>>(q, k, v, ctx);

    // 3. ctx @ wo + bo + x -> t1
    gemm_ca<EP_RESID><<<gD, 256, GEMM_SMEM>>>(ctx, woT, bo, x, t1, DMODEL, DMODEL, 1.0f);

    // 4. LN1 -> h (full) + hr (tf32)
    ln_kernel<<<MROWS, 256>>>(t1, g1, be1, hh, hr);

    // 5. GELU(hr @ w1 + b1) -> f1 (tf32)
    gemm_ca<EP_GELU_TF32><<<gF, 256, GEMM_SMEM>>>(hr, w1T, b1, nullptr, f1, DFF, DMODEL, 1.0f);

    // 6. f1 @ w2 + b2 + h -> t2
    gemm_ca<EP_RESID><<<gD, 256, GEMM_SMEM>>>(f1, w2T, b2, hh, t2, DMODEL, DFF, 1.0f);

    // 7. LN2 -> out
    ln_kernel<<<MROWS, 256>>>(t2, g2, be2, out, nullptr);
}

// round 11
// speedup vs baseline: 1.1158x; 1.1158x over previous
#include <cuda_runtime.h>
#include <cuda_bf16.h>
#include <math.h>
#include <stdint.h>

// Problem constants
#define BATCH 4
#define SEQ   2048
#define DMODEL 768
#define NHEAD 12
#define DHEAD 64
#define DFF   3072
#define MROWS (BATCH*SEQ)          // 8192
#define NQKV  (3*DMODEL)           // 2304
#define EPS   1e-5f

// ---------------------------------------------------------------------------
// Scratch (device globals; allocation-free contract)
// ---------------------------------------------------------------------------
__device__ float g_q  [(size_t)MROWS * DMODEL];   // tf32, pre-scaled 1/8
__device__ float g_k  [(size_t)MROWS * DMODEL];   // tf32
__device__ float g_v  [(size_t)MROWS * DMODEL];   // tf32
__device__ float g_ctx[(size_t)MROWS * DMODEL];   // tf32 (attn epilogue rounds)
__device__ float g_t1 [(size_t)MROWS * DMODEL];
__device__ float g_h  [(size_t)MROWS * DMODEL];   // full fp32 (residual)
__device__ float g_hr [(size_t)MROWS * DMODEL];   // tf32 (FFN1 A operand)
__device__ float g_f1 [(size_t)MROWS * DFF];      // tf32 (GELU epilogue rounds)
__device__ float g_t2 [(size_t)MROWS * DMODEL];
// pre-rounded operands
__device__ float g_xr  [(size_t)MROWS * DMODEL];
__device__ float g_wqkv[(size_t)DMODEL * NQKV];   // [768][2304] packed wq|wk|wv, tf32
__device__ float g_bqkv[NQKV];                    // packed bq|bk|bv
__device__ float g_wor [(size_t)DMODEL * DMODEL];
__device__ float g_w1r [(size_t)DMODEL * DFF];
__device__ float g_w2r [(size_t)DFF * DMODEL];

// ---------------------------------------------------------------------------
// tf32 helpers
// ---------------------------------------------------------------------------
__device__ __forceinline__ float f2tf32(float x)
{
    uint32_t u;
    asm("cvt.rna.tf32.f32 %0, %1;" : "=r"(u) : "f"(x));
    return __uint_as_float(u);
}

__device__ __forceinline__ void mma_tf32(float* c, const uint32_t* a, const uint32_t* b)
{
    asm volatile(
        "mma.sync.aligned.m16n8k8.row.col.f32.tf32.tf32.f32 "
        "{%0,%1,%2,%3},{%4,%5,%6,%7},{%8,%9},{%0,%1,%2,%3};\n"
        : "+f"(c[0]), "+f"(c[1]), "+f"(c[2]), "+f"(c[3])
        : "r"(a[0]), "r"(a[1]), "r"(a[2]), "r"(a[3]), "r"(b[0]), "r"(b[1]));
}

__device__ __forceinline__ uint32_t smem_u32(const void* p)
{
    return (uint32_t)__cvta_generic_to_shared(p);
}

#define CPA16(dst, src) \
    asm volatile("cp.async.cg.shared.global [%0], [%1], 16;\n" :: "r"(dst), "l"(src))
#define CPA_COMMIT() asm volatile("cp.async.commit_group;\n")
#define CPA_WAIT1()  asm volatile("cp.async.wait_group 1;\n")
#define CPA_WAIT0()  asm volatile("cp.async.wait_group 0;\n")

// ---------------------------------------------------------------------------
// Prep kernels
// ---------------------------------------------------------------------------
__global__ __launch_bounds__(256)
void round_tf32_kernel(const float* __restrict__ src, float* __restrict__ dst, int n4)
{
    const int i = blockIdx.x * blockDim.x + threadIdx.x;
    if (i < n4) {
        float4 v = *((const float4*)src + i);
        v.x = f2tf32(v.x); v.y = f2tf32(v.y);
        v.z = f2tf32(v.z); v.w = f2tf32(v.w);
        *((float4*)dst + i) = v;
    }
}

// round wq/wk/wv [768][768] into g_wqkv[768][2304] at column offset `off`
__global__ __launch_bounds__(256)
void round_pack_kernel(const float* __restrict__ src, float* __restrict__ dst, int off)
{
    const int i = blockIdx.x * blockDim.x + threadIdx.x;
    if (i < DMODEL * DMODEL / 4) {
        const int k  = i / (DMODEL / 4);
        const int n4 = i % (DMODEL / 4);
        float4 v = *((const float4*)src + i);
        v.x = f2tf32(v.x); v.y = f2tf32(v.y);
        v.z = f2tf32(v.z); v.w = f2tf32(v.w);
        *(float4*)(dst + (size_t)k * NQKV + off + n4 * 4) = v;
    }
}

__global__ __launch_bounds__(256)
void pack_bias_kernel(const float* __restrict__ src, float* __restrict__ dst, int off)
{
    const int i = blockIdx.x * blockDim.x + threadIdx.x;
    if (i < DMODEL) dst[off + i] = src[i];
}

// ---------------------------------------------------------------------------
// cp.async tf32 GEMM (R9 layout): C[M,N] = A[M,K] @ B[K,N] + bias (+epilogue).
// Operands MUST be pre-rounded tf32 in gmem.
// Template BM in {128, 64}; BN=128, BK=16, 256 threads (8 warps 2x4,
// warp tile (BM/2)x32). 3-stage cp.async pipeline.
// A smem [m][k] pitch 20; B smem [k][n] pitch 136 (both conflict-free).
// ---------------------------------------------------------------------------
enum { EP_RESID = 1, EP_GELU_TF32 = 2, EP_TF32 = 3, EP_QKV = 4 };

#define APITCH 20
#define BPITCH 136
#define BBUF   (16*BPITCH)    // 2176 floats
#define GEMM_SMEM_BM(BM) ((3*((BM)*APITCH) + 3*BBUF) * 4)

template<int EPI, int BM>
__global__ __launch_bounds__(256)
void gemm_ca(const float* __restrict__ A, const float* __restrict__ Bm,
             const float* __restrict__ bias, const float* __restrict__ resid,
             float* __restrict__ C, int Ndim, int Kdim, float oscale)
{
    constexpr int WROWS = BM / 2;       // rows per warp-row
    constexpr int MT    = WROWS / 16;   // m16 tiles per warp
    constexpr int ABUFT = BM * APITCH;

    extern __shared__ float gsm[];
    float* As = gsm;                 // [3][BM][APITCH]
    float* Bs = gsm + 3*ABUFT;       // [3][16][BPITCH]

    const int tid  = threadIdx.x;
    const int lane = tid & 31;
    const int warp = tid >> 5;
    const int wm = warp & 1;
    const int wn = warp >> 1;
    const int g = lane >> 2;
    const int q = lane & 3;
    const int row0 = blockIdx.y * BM;
    const int col0 = blockIdx.x * 128;

    // cp.async mappings (256 threads)
    const int br = tid >> 4;            // 0..15 B row
    const int bc8 = (tid & 15) * 8;     // B col base (floats)

    const uint32_t asu = smem_u32(As);
    const uint32_t bsu = smem_u32(Bs);

    float acc[MT][4][4];
    #pragma unroll
    for (int i = 0; i < MT; i++)
        #pragma unroll
        for (int j = 0; j < 4; j++)
            #pragma unroll
            for (int r = 0; r < 4; r++) acc[i][j][r] = 0.f;

    const int nk = Kdim >> 4;

    #define GISSUE(i, bf_) do {                                                     \
        const int k0_ = (i) << 4;                                                   \
        if (BM == 128) {                                                            \
            const int ar  = tid >> 1;                                               \
            const int ac8 = (tid & 1) * 8;                                          \
            const float* asrc = A + (size_t)(row0 + ar) * Kdim + k0_ + ac8;         \
            const uint32_t ad = asu + (uint32_t)((bf_)*ABUFT + ar*APITCH + ac8)*4u; \
            CPA16(ad,       asrc);                                                  \
            CPA16(ad + 16u, asrc + 4);                                              \
        } else {                                                                    \
            const int ar  = tid >> 2;                                               \
            const int ac4 = (tid & 3) * 4;                                          \
            const float* asrc = A + (size_t)(row0 + ar) * Kdim + k0_ + ac4;         \
            const uint32_t ad = asu + (uint32_t)((bf_)*ABUFT + ar*APITCH + ac4)*4u; \
            CPA16(ad, asrc);                                                        \
        }                                                                           \
        const float* bsrc = Bm + (size_t)(k0_ + br) * Ndim + col0 + bc8;            \
        const uint32_t bd = bsu + (uint32_t)((bf_)*BBUF + br*BPITCH + bc8) * 4u;    \
        CPA16(bd,       bsrc);                                                      \
        CPA16(bd + 16u, bsrc + 4);                                                  \
        CPA_COMMIT();                                                               \
    } while (0)

    #define GCOMPUTE(bf_) do {                                                    \
        const float* Ab = As + (bf_)*ABUFT;                                       \
        const float* Bb = Bs + (bf_)*BBUF;                                        \
        _Pragma("unroll")                                                         \
        for (int ks = 0; ks < 16; ks += 8) {                                      \
            uint32_t af[MT][4], bf2[4][2];                                        \
            _Pragma("unroll")                                                     \
            for (int mt = 0; mt < MT; mt++) {                                     \
                const int m0 = wm*WROWS + mt*16;                                  \
                af[mt][0] = __float_as_uint(Ab[(m0+g  )*APITCH + ks+q  ]);        \
                af[mt][1] = __float_as_uint(Ab[(m0+g+8)*APITCH + ks+q  ]);        \
                af[mt][2] = __float_as_uint(Ab[(m0+g  )*APITCH + ks+q+4]);        \
                af[mt][3] = __float_as_uint(Ab[(m0+g+8)*APITCH + ks+q+4]);        \
            }                                                                     \
            _Pragma("unroll")                                                     \
            for (int nt = 0; nt < 4; nt++) {                                      \
                const int n0 = wn*32 + nt*8;                                      \
                bf2[nt][0] = __float_as_uint(Bb[(ks+q  )*BPITCH + n0+g]);         \
                bf2[nt][1] = __float_as_uint(Bb[(ks+q+4)*BPITCH + n0+g]);         \
            }                                                                     \
            _Pragma("unroll")                                                     \
            for (int mt = 0; mt < MT; mt++)                                       \
                _Pragma("unroll")                                                 \
                for (int nt = 0; nt < 4; nt++)                                    \
                    mma_tf32(acc[mt][nt], af[mt], bf2[nt]);                       \
        }                                                                         \
    } while (0)

    GISSUE(0, 0);
    GISSUE(1, 1);

    for (int i = 0; i < nk; i++) {
        if (i + 1 < nk) { CPA_WAIT1(); } else { CPA_WAIT0(); }
        __syncthreads();
        const int cb = i % 3;
        GCOMPUTE(cb);
        if (i + 2 < nk) GISSUE(i + 2, (i + 2) % 3);
        __syncthreads();    // all warps done reading buf cb before it is reused
    }

    #undef GISSUE
    #undef GCOMPUTE

    // epilogue
    #pragma unroll
    for (int mt = 0; mt < MT; mt++) {
        const int mlo = row0 + wm*WROWS + mt*16 + g;
        #pragma unroll
        for (int nt = 0; nt < 4; nt++) {
            const int n = col0 + wn*32 + nt*8 + 2*q;
            const float b0 = bias[n], b1 = bias[n+1];
            #pragma unroll
            for (int half = 0; half < 2; half++) {
                const int m = mlo + half*8;
                float v0 = acc[mt][nt][half*2+0] + b0;
                float v1 = acc[mt][nt][half*2+1] + b1;
                if (EPI == EP_RESID) {
                    v0 += resid[(size_t)m * Ndim + n];
                    v1 += resid[(size_t)m * Ndim + n + 1];
                    *(float2*)(C + (size_t)m * Ndim + n) = make_float2(v0, v1);
                }
                if (EPI == EP_GELU_TF32) {
                    v0 = f2tf32(0.5f * v0 * (1.0f + erff(v0 * 0.70710678118654752f)));
                    v1 = f2tf32(0.5f * v1 * (1.0f + erff(v1 * 0.70710678118654752f)));
                    *(float2*)(C + (size_t)m * Ndim + n) = make_float2(v0, v1);
                }
                if (EPI == EP_TF32) {
                    v0 = f2tf32(v0 * oscale);
                    v1 = f2tf32(v1 * oscale);
                    *(float2*)(C + (size_t)m * Ndim + n) = make_float2(v0, v1);
                }
                if (EPI == EP_QKV) {
                    // scatter by n-segment into q/k/v (tiles never straddle 768)
                    float* dst;
                    int nc;
                    float sc;
                    if (n < DMODEL)        { dst = g_q; nc = n;            sc = 0.125f; }
                    else if (n < 2*DMODEL) { dst = g_k; nc = n -   DMODEL; sc = 1.0f;   }
                    else                   { dst = g_v; nc = n - 2*DMODEL; sc = 1.0f;   }
                    *(float2*)(dst + (size_t)m * DMODEL + nc) =
                        make_float2(f2tf32(v0 * sc), f2tf32(v1 * sc));
                }
            }
        }
    }
}

// ---------------------------------------------------------------------------
// Tensor-core flash attention (causal, tf32 mma). UNCHANGED from R9.
// CTA = 8 warps = 128 query rows of one (b,h). 64-key tiles, cp.async x2 buf.
// ---------------------------------------------------------------------------
#define PK 68
#define PV 72
#define PP 68
#define ATTN_SMEM ((2*64*PK + 2*64*PV + 128*PP) * 4)

__global__ __launch_bounds__(256, 2)
void attn_tc(const float* __restrict__ Q, const float* __restrict__ K,
             const float* __restrict__ V, float* __restrict__ ctx)
{
    extern __shared__ float sm[];
    float* Kb[2] = { sm, sm + 64*PK };
    float* Vb[2] = { sm + 2*64*PK, sm + 2*64*PK + 64*PV };
    float* Ps    = sm + 2*64*PK + 2*64*PV;      // [128][PP], also Q staging

    const int bh = blockIdx.y;
    const int b  = bh / NHEAD;
    const int h  = bh % NHEAD;
    const int qt = (SEQ/128 - 1) - blockIdx.x;  // heavy CTAs first
    const int tid  = threadIdx.x;
    const int warp = tid >> 5;
    const int lane = tid & 31;
    const int g = lane >> 2;
    const int q = lane & 3;
    const int wrow = warp * 16;                 // 0..112
    const int qbase = qt * 128;

    const int lr = tid >> 2;                    // 0..63
    const int cb = (tid & 3) * 4;               // float4 chunk base

    const uint32_t kbu[2] = { smem_u32(Kb[0]), smem_u32(Kb[1]) };
    const uint32_t vbu[2] = { smem_u32(Vb[0]), smem_u32(Vb[1]) };

    #define ISSUE_TILE(kb, sel) do {                                                 \
        const float* kbase = K + ((size_t)(b*SEQ + (kb)*64 + lr))*DMODEL + h*DHEAD;  \
        const float* vbase = V + ((size_t)(b*SEQ + (kb)*64 + lr))*DMODEL + h*DHEAD;  \
        const uint32_t kd = kbu[sel] + (uint32_t)(lr*PK)*4u + (uint32_t)cb*16u;      \
        const uint32_t vd = vbu[sel] + (uint32_t)(lr*PV)*4u + (uint32_t)cb*16u;      \
        _Pragma("unroll")                                                            \
        for (int i = 0; i < 4; i++) {                                                \
            CPA16(kd + i*16u, kbase + (cb + i)*4);                                   \
            CPA16(vd + i*16u, vbase + (cb + i)*4);                                   \
        }                                                                            \
        CPA_COMMIT();                                                                \
    } while (0)

    ISSUE_TILE(0, 0);

    // ---- stage Q (128 rows) through Ps, read fragments into registers ----
    {
        const int qlr = tid >> 1;
        const int qlc = (tid & 1) * 8;
        const float* qsrc = Q + ((size_t)(b*SEQ + qbase + qlr))*DMODEL + h*DHEAD;
        #pragma unroll
        for (int i = 0; i < 8; i++)
            *(float4*)&Ps[qlr*PP + (qlc + i)*4] = *(const float4*)(qsrc + (qlc + i)*4);
    }
    __syncthreads();
    uint32_t qf[8][4];
    #pragma unroll
    for (int ks8 = 0; ks8 < 8; ks8++) {
        qf[ks8][0] = __float_as_uint(Ps[(wrow+g  )*PP + ks8*8 + q  ]);
        qf[ks8][1] = __float_as_uint(Ps[(wrow+g+8)*PP + ks8*8 + q  ]);
        qf[ks8][2] = __float_as_uint(Ps[(wrow+g  )*PP + ks8*8 + q+4]);
        qf[ks8][3] = __float_as_uint(Ps[(wrow+g+8)*PP + ks8*8 + q+4]);
    }
    __syncthreads();

    float oacc[8][4];
    #pragma unroll
    for (int nt = 0; nt < 8; nt++)
        #pragma unroll
        for (int e = 0; e < 4; e++) oacc[nt][e] = 0.f;
    float m0 = -1e30f, m1 = -1e30f, l0 = 0.f, l1 = 0.f;

    const int nkb = 2*qt + 2;

    for (int kb = 0; kb < nkb; kb++) {
        const int cur = kb & 1;
        if (kb + 1 < nkb) {
            ISSUE_TILE(kb + 1, cur ^ 1);
            CPA_WAIT1();
        } else {
            CPA_WAIT0();
        }
        __syncthreads();

        const bool skip = (kb*64) > (qbase + wrow + 15);
        if (!skip) {
            const float* Ksm = Kb[cur];
            const float* Vsm = Vb[cur];

            float sacc[8][4];
            #pragma unroll
            for (int nt = 0; nt < 8; nt++)
                #pragma unroll
                for (int e = 0; e < 4; e++) sacc[nt][e] = 0.f;

            #pragma unroll
            for (int ks8 = 0; ks8 < 8; ks8++) {
                const int ks = ks8 * 8;
                #pragma unroll
                for (int nt = 0; nt < 8; nt++) {
                    uint32_t bb[2];
                    bb[0] = __float_as_uint(Ksm[(nt*8+g)*PK + ks+q  ]);
                    bb[1] = __float_as_uint(Ksm[(nt*8+g)*PK + ks+q+4]);
                    mma_tf32(sacc[nt], qf[ks8], bb);
                }
            }

            if (kb*64 + 63 > qbase + wrow) {
                const int r0 = qbase + wrow + g;
                const int r1 = r0 + 8;
                #pragma unroll
                for (int nt = 0; nt < 8; nt++) {
                    const int colg = kb*64 + nt*8 + 2*q;
                    if (colg     > r0) sacc[nt][0] = -1e30f;
                    if (colg + 1 > r0) sacc[nt][1] = -1e30f;
                    if (colg     > r1) sacc[nt][2] = -1e30f;
                    if (colg + 1 > r1) sacc[nt][3] = -1e30f;
                }
            }

            float rm0 = -1e30f, rm1 = -1e30f;
            #pragma unroll
            for (int nt = 0; nt < 8; nt++) {
                rm0 = fmaxf(rm0, fmaxf(sacc[nt][0], sacc[nt][1]));
                rm1 = fmaxf(rm1, fmaxf(sacc[nt][2], sacc[nt][3]));
            }
            rm0 = fmaxf(rm0, __shfl_xor_sync(0xffffffffu, rm0, 1));
            rm0 = fmaxf(rm0, __shfl_xor_sync(0xffffffffu, rm0, 2));
            rm1 = fmaxf(rm1, __shfl_xor_sync(0xffffffffu, rm1, 1));
            rm1 = fmaxf(rm1, __shfl_xor_sync(0xffffffffu, rm1, 2));

            const float mn0 = fmaxf(m0, rm0);
            const float mn1 = fmaxf(m1, rm1);
            const float c0 = __expf(m0 - mn0);
            const float c1 = __expf(m1 - mn1);
            m0 = mn0; m1 = mn1;

            float s0 = 0.f, s1 = 0.f;
            #pragma unroll
            for (int nt = 0; nt < 8; nt++) {
                float p;
                p = __expf(sacc[nt][0] - mn0); s0 += p; sacc[nt][0] = p;
                p = __expf(sacc[nt][1] - mn0); s0 += p; sacc[nt][1] = p;
                p = __expf(sacc[nt][2] - mn1); s1 += p; sacc[nt][2] = p;
                p = __expf(sacc[nt][3] - mn1); s1 += p; sacc[nt][3] = p;
            }
            s0 += __shfl_xor_sync(0xffffffffu, s0, 1);
            s0 += __shfl_xor_sync(0xffffffffu, s0, 2);
            s1 += __shfl_xor_sync(0xffffffffu, s1, 1);
            s1 += __shfl_xor_sync(0xffffffffu, s1, 2);
            l0 = l0 * c0 + s0;
            l1 = l1 * c1 + s1;

            #pragma unroll
            for (int nt = 0; nt < 8; nt++) {
                oacc[nt][0] *= c0; oacc[nt][1] *= c0;
                oacc[nt][2] *= c1; oacc[nt][3] *= c1;
            }

            #pragma unroll
            for (int nt = 0; nt < 8; nt++) {
                *(float2*)&Ps[(wrow+g  )*PP + nt*8 + 2*q] =
                    make_float2(f2tf32(sacc[nt][0]), f2tf32(sacc[nt][1]));
                *(float2*)&Ps[(wrow+g+8)*PP + nt*8 + 2*q] =
                    make_float2(f2tf32(sacc[nt][2]), f2tf32(sacc[nt][3]));
            }
            __syncwarp();

            #pragma unroll
            for (int ks8 = 0; ks8 < 8; ks8++) {
                const int ks = ks8 * 8;
                uint32_t a[4];
                a[0] = __float_as_uint(Ps[(wrow+g  )*PP + ks+q  ]);
                a[1] = __float_as_uint(Ps[(wrow+g+8)*PP + ks+q  ]);
                a[2] = __float_as_uint(Ps[(wrow+g  )*PP + ks+q+4]);
                a[3] = __float_as_uint(Ps[(wrow+g+8)*PP + ks+q+4]);
                #pragma unroll
                for (int nt = 0; nt < 8; nt++) {
                    uint32_t bb[2];
                    bb[0] = __float_as_uint(Vsm[(ks+q  )*PV + nt*8+g]);
                    bb[1] = __float_as_uint(Vsm[(ks+q+4)*PV + nt*8+g]);
                    mma_tf32(oacc[nt], a, bb);
                }
            }
        }
        __syncthreads();
    }
    #undef ISSUE_TILE

    const float i0 = 1.f / l0;
    const float i1 = 1.f / l1;
    float* c0p = ctx + ((size_t)(b*SEQ + qbase + wrow + g    )) * DMODEL + h*DHEAD;
    float* c1p = ctx + ((size_t)(b*SEQ + qbase + wrow + g + 8)) * DMODEL + h*DHEAD;
    #pragma unroll
    for (int nt = 0; nt < 8; nt++) {
        *(float2*)(c0p + nt*8 + 2*q) =
            make_float2(f2tf32(oacc[nt][0]*i0), f2tf32(oacc[nt][1]*i0));
        *(float2*)(c1p + nt*8 + 2*q) =
            make_float2(f2tf32(oacc[nt][2]*i1), f2tf32(oacc[nt][3]*i1));
    }
}

// ---------------------------------------------------------------------------
// Row-wise LayerNorm over 768 elems. 256 threads/row.
// ---------------------------------------------------------------------------
__global__ __launch_bounds__(256)
void ln_kernel(const float* __restrict__ X, const float* __restrict__ g,
               const float* __restrict__ be, float* __restrict__ Y,
               float* __restrict__ Yr)
{
    __shared__ float red[8];
    const int row = blockIdx.x;
    const int tid = threadIdx.x;
    const float* x = X + (size_t)row * DMODEL;

    float v[3];
    float s = 0.f;
    #pragma unroll
    for (int i = 0; i < 3; i++) { v[i] = x[tid + i * 256]; s += v[i]; }

    #pragma unroll
    for (int off = 16; off; off >>= 1) s += __shfl_xor_sync(0xffffffffu, s, off);
    if ((tid & 31) == 0) red[tid >> 5] = s;
    __syncthreads();
    float total = 0.f;
    #pragma unroll
    for (int i = 0; i < 8; i++) total += red[i];
    const float mean = total * (1.0f / DMODEL);
    __syncthreads();

    float s2 = 0.f;
    #pragma unroll
    for (int i = 0; i < 3; i++) { const float d = v[i] - mean; s2 += d * d; }
    #pragma unroll
    for (int off = 16; off; off >>= 1) s2 += __shfl_xor_sync(0xffffffffu, s2, off);
    if ((tid & 31) == 0) red[tid >> 5] = s2;
    __syncthreads();
    float tot2 = 0.f;
    #pragma unroll
    for (int i = 0; i < 8; i++) tot2 += red[i];
    const float rstd = rsqrtf(tot2 * (1.0f / DMODEL) + EPS);

    #pragma unroll
    for (int i = 0; i < 3; i++) {
        const int c = tid + i * 256;
        const float y = (v[i] - mean) * rstd * g[c] + be[c];
        Y[(size_t)row * DMODEL + c] = y;
        if (Yr) Yr[(size_t)row * DMODEL + c] = f2tf32(y);
    }
}

// ---------------------------------------------------------------------------
// Launch
// ---------------------------------------------------------------------------
static float* sym_addr(const void* sym)
{
    void* p = nullptr;
    cudaGetSymbolAddress(&p, sym);
    return (float*)p;
}

extern "C" void kernel_launch(void* const* d_in, const int* in_sizes, int n_in,
                              void* d_out, int out_size)
{
    const float* x   = (const float*)d_in[0];
    // d_in[1] = mask (causal; implied)
    const float* wq  = (const float*)d_in[2];
    const float* bq  = (const float*)d_in[3];
    const float* wk  = (const float*)d_in[4];
    const float* bk  = (const float*)d_in[5];
    const float* wv  = (const float*)d_in[6];
    const float* bv  = (const float*)d_in[7];
    const float* wo  = (const float*)d_in[8];
    const float* bo  = (const float*)d_in[9];
    const float* g1  = (const float*)d_in[10];
    const float* be1 = (const float*)d_in[11];
    const float* w1  = (const float*)d_in[12];
    const float* b1  = (const float*)d_in[13];
    const float* w2  = (const float*)d_in[14];
    const float* b2  = (const float*)d_in[15];
    const float* g2  = (const float*)d_in[16];
    const float* be2 = (const float*)d_in[17];
    float* out = (float*)d_out;

    float* q    = sym_addr(g_q);
    float* k    = sym_addr(g_k);
    float* v    = sym_addr(g_v);
    float* ctx  = sym_addr(g_ctx);
    float* t1   = sym_addr(g_t1);
    float* hh   = sym_addr(g_h);
    float* hr   = sym_addr(g_hr);
    float* f1   = sym_addr(g_f1);
    float* t2   = sym_addr(g_t2);
    float* xr   = sym_addr(g_xr);
    float* wqkv = sym_addr(g_wqkv);
    float* bqkv = sym_addr(g_bqkv);
    float* wor  = sym_addr(g_wor);
    float* w1r  = sym_addr(g_w1r);
    float* w2r  = sym_addr(g_w2r);

    cudaFuncSetAttribute(attn_tc, cudaFuncAttributeMaxDynamicSharedMemorySize,
                         ATTN_SMEM);
    cudaFuncSetAttribute(gemm_ca<EP_QKV, 128>,
                         cudaFuncAttributeMaxDynamicSharedMemorySize, GEMM_SMEM_BM(128));
    cudaFuncSetAttribute(gemm_ca<EP_RESID, 64>,
                         cudaFuncAttributeMaxDynamicSharedMemorySize, GEMM_SMEM_BM(64));
    cudaFuncSetAttribute(gemm_ca<EP_GELU_TF32, 64>,
                         cudaFuncAttributeMaxDynamicSharedMemorySize, GEMM_SMEM_BM(64));

    // 0. prep: round x; pack+round qkv weights/bias; round wo/w1/w2
    const int nX = MROWS * DMODEL / 4;
    const int nW = DMODEL * DMODEL / 4;
    const int nW1 = DMODEL * DFF / 4;
    round_tf32_kernel<<<(nX + 255)/256, 256>>>(x, xr, nX);
    round_pack_kernel<<<(nW + 255)/256, 256>>>(wq, wqkv, 0);
    round_pack_kernel<<<(nW + 255)/256, 256>>>(wk, wqkv, DMODEL);
    round_pack_kernel<<<(nW + 255)/256, 256>>>(wv, wqkv, 2*DMODEL);
    pack_bias_kernel<<<3, 256>>>(bq, bqkv, 0);
    pack_bias_kernel<<<3, 256>>>(bk, bqkv, DMODEL);
    pack_bias_kernel<<<3, 256>>>(bv, bqkv, 2*DMODEL);
    round_tf32_kernel<<<(nW  + 255)/256, 256>>>(wo, wor, nW);
    round_tf32_kernel<<<(nW1 + 255)/256, 256>>>(w1, w1r, nW1);
    round_tf32_kernel<<<(nW1 + 255)/256, 256>>>(w2, w2r, nW1);

    // 1. Fused QKV projection -> q/k/v (tf32, q pre-scaled 1/8)
    //    grid 18 x 64 = 1152 tiles (3.89 -> 4 waves)
    gemm_ca<EP_QKV, 128><<<dim3(NQKV/128, MROWS/128), 256, GEMM_SMEM_BM(128)>>>(
        xr, wqkv, bqkv, nullptr, q, NQKV, DMODEL, 1.0f);

    // 2. Causal flash attention -> ctx (tf32)
    attn_tc<<<dim3(SEQ/128, BATCH*NHEAD), 256, ATTN_SMEM>>>(q, k, v, ctx);

    // 3. ctx @ wo + bo + x -> t1   (BM=64: 768 tiles, 2.59 -> 3 waves)
    gemm_ca<EP_RESID, 64><<<dim3(DMODEL/128, MROWS/64), 256, GEMM_SMEM_BM(64)>>>(
        ctx, wor, bo, x, t1, DMODEL, DMODEL, 1.0f);

    // 4. LN1 -> h (full) + hr (tf32)
    ln_kernel<<<MROWS, 256>>>(t1, g1, be1, hh, hr);

    // 5. GELU(hr @ w1 + b1) -> f1  (BM=64: 3072 tiles, 10.4 -> 11 waves)
    gemm_ca<EP_GELU_TF32, 64><<<dim3(DFF/128, MROWS/64), 256, GEMM_SMEM_BM(64)>>>(
        hr, w1r, b1, nullptr, f1, DFF, DMODEL, 1.0f);

    // 6. f1 @ w2 + b2 + h -> t2   (BM=64: 768 tiles)
    gemm_ca<EP_RESID, 64><<<dim3(DMODEL/128, MROWS/64), 256, GEMM_SMEM_BM(64)>>>(
        f1, w2r, b2, hh, t2, DMODEL, DFF, 1.0f);

    // 7. LN2 -> out
    ln_kernel<<<MROWS, 256>>>(t2, g2, be2, out, nullptr);
}

// round 14
// speedup vs baseline: 1.2887x; 1.1549x over previous
#include <cuda_runtime.h>
#include <cuda_bf16.h>
#include <math.h>
#include <stdint.h>

// Problem constants
#define BATCH 4
#define SEQ   2048
#define DMODEL 768
#define NHEAD 12
#define DHEAD 64
#define DFF   3072
#define MROWS (BATCH*SEQ)          // 8192
#define NQKV  (3*DMODEL)           // 2304
#define EPS   1e-5f

// ---------------------------------------------------------------------------
// Scratch (device globals; allocation-free contract)
// ---------------------------------------------------------------------------
__device__ __nv_bfloat16 g_qb [(size_t)MROWS * DMODEL];   // bf16, pre-scaled 1/8
__device__ __nv_bfloat16 g_kb [(size_t)MROWS * DMODEL];   // bf16
__device__ __nv_bfloat16 g_vb [(size_t)MROWS * DMODEL];   // bf16 [b,s,h*d]
__device__ __nv_bfloat16 g_vT [(size_t)MROWS * DMODEL];   // bf16 [b][h*d][s]
__device__ float g_ctx[(size_t)MROWS * DMODEL];   // tf32 (WO A operand)
__device__ float g_t1 [(size_t)MROWS * DMODEL];
__device__ float g_h  [(size_t)MROWS * DMODEL];   // full fp32 (residual)
__device__ float g_hr [(size_t)MROWS * DMODEL];   // tf32 (FFN1 A operand)
__device__ float g_f1 [(size_t)MROWS * DFF];      // tf32 (FFN2 A operand)
__device__ float g_t2 [(size_t)MROWS * DMODEL];
// tf32 operands
__device__ float g_xr  [(size_t)MROWS * DMODEL];
__device__ float g_wqkv[(size_t)DMODEL * NQKV];   // [768][2304] packed, tf32
__device__ float g_bqkv[NQKV];
__device__ float g_wor [(size_t)DMODEL * DMODEL];
__device__ float g_w1r [(size_t)DMODEL * DFF];
__device__ float g_w2r [(size_t)DFF * DMODEL];

// ---------------------------------------------------------------------------
// helpers
// ---------------------------------------------------------------------------
__device__ __forceinline__ float f2tf32(float x)
{
    uint32_t u;
    asm("cvt.rna.tf32.f32 %0, %1;" : "=r"(u) : "f"(x));
    return __uint_as_float(u);
}

__device__ __forceinline__ void mma_tf32(float* c, const uint32_t* a, const uint32_t* b)
{
    asm volatile(
        "mma.sync.aligned.m16n8k8.row.col.f32.tf32.tf32.f32 "
        "{%0,%1,%2,%3},{%4,%5,%6,%7},{%8,%9},{%0,%1,%2,%3};\n"
        : "+f"(c[0]), "+f"(c[1]), "+f"(c[2]), "+f"(c[3])
        : "r"(a[0]), "r"(a[1]), "r"(a[2]), "r"(a[3]), "r"(b[0]), "r"(b[1]));
}

__device__ __forceinline__ void mma_bf16(float* c, const uint32_t* a, const uint32_t* b)
{
    asm volatile(
        "mma.sync.aligned.m16n8k16.row.col.f32.bf16.bf16.f32 "
        "{%0,%1,%2,%3},{%4,%5,%6,%7},{%8,%9},{%0,%1,%2,%3};\n"
        : "+f"(c[0]), "+f"(c[1]), "+f"(c[2]), "+f"(c[3])
        : "r"(a[0]), "r"(a[1]), "r"(a[2]), "r"(a[3]), "r"(b[0]), "r"(b[1]));
}

__device__ __forceinline__ uint32_t smem_u32(const void* p)
{
    return (uint32_t)__cvta_generic_to_shared(p);
}

#define CPA16(dst, src) \
    asm volatile("cp.async.cg.shared.global [%0], [%1], 16;\n" :: "r"(dst), "l"(src))
#define CPA_COMMIT() asm volatile("cp.async.commit_group;\n")
#define CPA_WAIT1()  asm volatile("cp.async.wait_group 1;\n")
#define CPA_WAIT0()  asm volatile("cp.async.wait_group 0;\n")

// ---------------------------------------------------------------------------
// Prep kernels
// ---------------------------------------------------------------------------
__global__ __launch_bounds__(256)
void round_tf32_kernel(const float* __restrict__ src, float* __restrict__ dst, int n4)
{
    const int i = blockIdx.x * blockDim.x + threadIdx.x;
    if (i < n4) {
        float4 v = *((const float4*)src + i);
        v.x = f2tf32(v.x); v.y = f2tf32(v.y);
        v.z = f2tf32(v.z); v.w = f2tf32(v.w);
        *((float4*)dst + i) = v;
    }
}

__global__ __launch_bounds__(256)
void round_pack_kernel(const float* __restrict__ src, float* __restrict__ dst, int off)
{
    const int i = blockIdx.x * blockDim.x + threadIdx.x;
    if (i < DMODEL * DMODEL / 4) {
        const int k  = i / (DMODEL / 4);
        const int n4 = i % (DMODEL / 4);
        float4 v = *((const float4*)src + i);
        v.x = f2tf32(v.x); v.y = f2tf32(v.y);
        v.z = f2tf32(v.z); v.w = f2tf32(v.w);
        *(float4*)(dst + (size_t)k * NQKV + off + n4 * 4) = v;
    }
}

__global__ __launch_bounds__(256)
void pack_bias_kernel(const float* __restrict__ src, float* __restrict__ dst, int off)
{
    const int i = blockIdx.x * blockDim.x + threadIdx.x;
    if (i < DMODEL) dst[off + i] = src[i];
}

// V [b,s,768] bf16 -> vT [b][768][2048] bf16 (per-batch transpose)
__global__ __launch_bounds__(256)
void transposeV_kernel(const __nv_bfloat16* __restrict__ src,
                       __nv_bfloat16* __restrict__ dst)
{
    __shared__ __nv_bfloat16 t[32][33];
    const int s0 = blockIdx.x * 32;
    const int c0 = blockIdx.y * 32;
    const int b  = blockIdx.z;
    const int x = threadIdx.x;
    const int y = threadIdx.y;
    #pragma unroll
    for (int i = 0; i < 32; i += 8)
        t[y + i][x] = src[((size_t)(b*SEQ + s0 + y + i)) * DMODEL + c0 + x];
    __syncthreads();
    #pragma unroll
    for (int i = 0; i < 32; i += 8)
        dst[((size_t)(b*DMODEL + c0 + y + i)) * SEQ + s0 + x] = t[x][y + i];
}

// ---------------------------------------------------------------------------
// tf32 cp.async GEMM (verified R11): C = A[M,K] @ B[K,N] + bias (+epilogue).
// BM in {128,64}; BN=128, BK=16, 256 threads, warp tile (BM/2)x32.
// A smem [m][k] pitch 20; B smem [k][n] pitch 136.
// EP_QKV scatters bf16 q/k/v.
// ---------------------------------------------------------------------------
enum { EP_RESID = 1, EP_GELU_TF32 = 2, EP_QKV = 4 };

#define APITCH 20
#define BPITCH 136
#define BBUF   (16*BPITCH)
#define GEMM_SMEM_BM(BM) ((3*((BM)*APITCH) + 3*BBUF) * 4)

template<int EPI, int BM>
__global__ __launch_bounds__(256)
void gemm_ca(const float* __restrict__ A, const float* __restrict__ Bm,
             const float* __restrict__ bias, const float* __restrict__ resid,
             float* __restrict__ C, int Ndim, int Kdim)
{
    constexpr int WROWS = BM / 2;
    constexpr int MT    = WROWS / 16;
    constexpr int ABUFT = BM * APITCH;

    extern __shared__ float gsm[];
    float* As = gsm;
    float* Bs = gsm + 3*ABUFT;

    const int tid  = threadIdx.x;
    const int lane = tid & 31;
    const int warp = tid >> 5;
    const int wm = warp & 1;
    const int wn = warp >> 1;
    const int g = lane >> 2;
    const int q = lane & 3;
    const int row0 = blockIdx.y * BM;
    const int col0 = blockIdx.x * 128;

    const int br = tid >> 4;
    const int bc8 = (tid & 15) * 8;

    const uint32_t asu = smem_u32(As);
    const uint32_t bsu = smem_u32(Bs);

    float acc[MT][4][4];
    #pragma unroll
    for (int i = 0; i < MT; i++)
        #pragma unroll
        for (int j = 0; j < 4; j++)
            #pragma unroll
            for (int r = 0; r < 4; r++) acc[i][j][r] = 0.f;

    const int nk = Kdim >> 4;

    #define GISSUE(i, bf_) do {                                                     \
        const int k0_ = (i) << 4;                                                   \
        if (BM == 128) {                                                            \
            const int ar  = tid >> 1;                                               \
            const int ac8 = (tid & 1) * 8;                                          \
            const float* asrc = A + (size_t)(row0 + ar) * Kdim + k0_ + ac8;         \
            const uint32_t ad = asu + (uint32_t)((bf_)*ABUFT + ar*APITCH + ac8)*4u; \
            CPA16(ad,       asrc);                                                  \
            CPA16(ad + 16u, asrc + 4);                                              \
        } else {                                                                    \
            const int ar  = tid >> 2;                                               \
            const int ac4 = (tid & 3) * 4;                                          \
            const float* asrc = A + (size_t)(row0 + ar) * Kdim + k0_ + ac4;         \
            const uint32_t ad = asu + (uint32_t)((bf_)*ABUFT + ar*APITCH + ac4)*4u; \
            CPA16(ad, asrc);                                                        \
        }                                                                           \
        const float* bsrc = Bm + (size_t)(k0_ + br) * Ndim + col0 + bc8;            \
        const uint32_t bd = bsu + (uint32_t)((bf_)*BBUF + br*BPITCH + bc8) * 4u;    \
        CPA16(bd,       bsrc);                                                      \
        CPA16(bd + 16u, bsrc + 4);                                                  \
        CPA_COMMIT();                                                               \
    } while (0)

    #define GCOMPUTE(bf_) do {                                                    \
        const float* Ab = As + (bf_)*ABUFT;                                       \
        const float* Bb = Bs + (bf_)*BBUF;                                        \
        _Pragma("unroll")                                                         \
        for (int ks = 0; ks < 16; ks += 8) {                                      \
            uint32_t af[MT][4], bf2[4][2];                                        \
            _Pragma("unroll")                                                     \
            for (int mt = 0; mt < MT; mt++) {                                     \
                const int m0 = wm*WROWS + mt*16;                                  \
                af[mt][0] = __float_as_uint(Ab[(m0+g  )*APITCH + ks+q  ]);        \
                af[mt][1] = __float_as_uint(Ab[(m0+g+8)*APITCH + ks+q  ]);        \
                af[mt][2] = __float_as_uint(Ab[(m0+g  )*APITCH + ks+q+4]);        \
                af[mt][3] = __float_as_uint(Ab[(m0+g+8)*APITCH + ks+q+4]);        \
            }                                                                     \
            _Pragma("unroll")                                                     \
            for (int nt = 0; nt < 4; nt++) {                                      \
                const int n0 = wn*32 + nt*8;                                      \
                bf2[nt][0] = __float_as_uint(Bb[(ks+q  )*BPITCH + n0+g]);         \
                bf2[nt][1] = __float_as_uint(Bb[(ks+q+4)*BPITCH + n0+g]);         \
            }                                                                     \
            _Pragma("unroll")                                                     \
            for (int mt = 0; mt < MT; mt++)                                       \
                _Pragma("unroll")                                                 \
                for (int nt = 0; nt < 4; nt++)                                    \
                    mma_tf32(acc[mt][nt], af[mt], bf2[nt]);                       \
        }                                                                         \
    } while (0)

    GISSUE(0, 0);
    GISSUE(1, 1);

    for (int i = 0; i < nk; i++) {
        if (i + 1 < nk) { CPA_WAIT1(); } else { CPA_WAIT0(); }
        __syncthreads();
        const int cb = i % 3;
        GCOMPUTE(cb);
        if (i + 2 < nk) GISSUE(i + 2, (i + 2) % 3);
        __syncthreads();
    }

    #undef GISSUE
    #undef GCOMPUTE

    #pragma unroll
    for (int mt = 0; mt < MT; mt++) {
        const int mlo = row0 + wm*WROWS + mt*16 + g;
        #pragma unroll
        for (int nt = 0; nt < 4; nt++) {
            const int n = col0 + wn*32 + nt*8 + 2*q;
            const float b0 = bias[n], b1 = bias[n+1];
            #pragma unroll
            for (int half = 0; half < 2; half++) {
                const int m = mlo + half*8;
                float v0 = acc[mt][nt][half*2+0] + b0;
                float v1 = acc[mt][nt][half*2+1] + b1;
                if (EPI == EP_RESID) {
                    v0 += resid[(size_t)m * Ndim + n];
                    v1 += resid[(size_t)m * Ndim + n + 1];
                    *(float2*)(C + (size_t)m * Ndim + n) = make_float2(v0, v1);
                }
                if (EPI == EP_GELU_TF32) {
                    v0 = f2tf32(0.5f * v0 * (1.0f + erff(v0 * 0.70710678118654752f)));
                    v1 = f2tf32(0.5f * v1 * (1.0f + erff(v1 * 0.70710678118654752f)));
                    *(float2*)(C + (size_t)m * Ndim + n) = make_float2(v0, v1);
                }
                if (EPI == EP_QKV) {
                    __nv_bfloat16* dst;
                    int nc;
                    float sc;
                    if (n < DMODEL)        { dst = g_qb; nc = n;            sc = 0.125f; }
                    else if (n < 2*DMODEL) { dst = g_kb; nc = n -   DMODEL; sc = 1.0f;   }
                    else                   { dst = g_vb; nc = n - 2*DMODEL; sc = 1.0f;   }
                    *(__nv_bfloat162*)(dst + (size_t)m * DMODEL + nc) =
                        __floats2bfloat162_rn(v0 * sc, v1 * sc);
                }
            }
        }
    }
}

// ---------------------------------------------------------------------------
// Tensor-core flash attention (causal, bf16 mma, fp32 softmax).
// CTA = 8 warps = 128 query rows of one (b,h). 64-key tiles, cp.async x2 buf.
// Q/K bf16 [b,s,h*d]; V transposed bf16 [b][h*d][s].
// ---------------------------------------------------------------------------
#define AP 72   // halves pitch
#define ATTN_SMEM ((2*64*AP + 2*64*AP + 128*AP) * 2)   // 55296 B

__global__ __launch_bounds__(256, 2)
void attn_bf(const __nv_bfloat16* __restrict__ Q, const __nv_bfloat16* __restrict__ K,
             const __nv_bfloat16* __restrict__ Vt, float* __restrict__ ctx)
{
    extern __shared__ __align__(16) char smraw[];
    __nv_bfloat16* sm = (__nv_bfloat16*)smraw;
    __nv_bfloat16* Kb[2] = { sm,            sm + 64*AP };
    __nv_bfloat16* Vb[2] = { sm + 2*64*AP,  sm + 3*64*AP };
    __nv_bfloat16* Ps    = sm + 4*64*AP;    // [128][AP], also Q staging

    const int bh = blockIdx.y;
    const int b  = bh / NHEAD;
    const int h  = bh % NHEAD;
    const int qt = (SEQ/128 - 1) - blockIdx.x;
    const int tid  = threadIdx.x;
    const int warp = tid >> 5;
    const int lane = tid & 31;
    const int g = lane >> 2;
    const int q = lane & 3;
    const int wrow = warp * 16;
    const int qbase = qt * 128;

    // tile load mapping: 4 threads per row, 16 halves (32 B) each
    const int lr = tid >> 2;                // 0..63
    const int cb = (tid & 3) * 16;          // halves

    const uint32_t kbu[2] = { smem_u32(Kb[0]), smem_u32(Kb[1]) };
    const uint32_t vbu[2] = { smem_u32(Vb[0]), smem_u32(Vb[1]) };

    #define ISSUE_TILE(kb, sel) do {                                                        \
        const __nv_bfloat16* ksrc =                                                         \
            K  + ((size_t)(b*SEQ + (kb)*64 + lr))*DMODEL + h*DHEAD + cb;                    \
        const __nv_bfloat16* vsrc =                                                         \
            Vt + ((size_t)(b*DMODEL + h*DHEAD + lr))*SEQ + (kb)*64 + cb;                    \
        const uint32_t kd = kbu[sel] + (uint32_t)(lr*AP + cb) * 2u;                         \
        const uint32_t vd = vbu[sel] + (uint32_t)(lr*AP + cb) * 2u;                         \
        CPA16(kd,       ksrc);                                                              \
        CPA16(kd + 16u, ksrc + 8);                                                          \
        CPA16(vd,       vsrc);                                                              \
        CPA16(vd + 16u, vsrc + 8);                                                          \
        CPA_COMMIT();                                                                       \
    } while (0)

    ISSUE_TILE(0, 0);

    // ---- stage Q (128 rows x 64 halves) through Ps, read fragments ----
    {
        const int qlr = tid >> 1;
        const int qlc = (tid & 1) * 32;     // halves
        const __nv_bfloat16* qsrc =
            Q + ((size_t)(b*SEQ + qbase + qlr))*DMODEL + h*DHEAD + qlc;
        #pragma unroll
        for (int i = 0; i < 4; i++)
            *(uint4*)&Ps[qlr*AP + qlc + i*8] = *(const uint4*)(qsrc + i*8);
    }
    __syncthreads();
    uint32_t qf[4][4];
    #pragma unroll
    for (int ks = 0; ks < 4; ks++) {
        qf[ks][0] = *(const uint32_t*)&Ps[(wrow+g  )*AP + ks*16 + 2*q    ];
        qf[ks][1] = *(const uint32_t*)&Ps[(wrow+g+8)*AP + ks*16 + 2*q    ];
        qf[ks][2] = *(const uint32_t*)&Ps[(wrow+g  )*AP + ks*16 + 2*q + 8];
        qf[ks][3] = *(const uint32_t*)&Ps[(wrow+g+8)*AP + ks*16 + 2*q + 8];
    }
    __syncthreads();

    float oacc[8][4];
    #pragma unroll
    for (int nt = 0; nt < 8; nt++)
        #pragma unroll
        for (int e = 0; e < 4; e++) oacc[nt][e] = 0.f;
    float m0 = -1e30f, m1 = -1e30f, l0 = 0.f, l1 = 0.f;

    const int nkb = 2*qt + 2;

    for (int kb = 0; kb < nkb; kb++) {
        const int cur = kb & 1;
        if (kb + 1 < nkb) {
            ISSUE_TILE(kb + 1, cur ^ 1);
            CPA_WAIT1();
        } else {
            CPA_WAIT0();
        }
        __syncthreads();

        const bool skip = (kb*64) > (qbase + wrow + 15);
        if (!skip) {
            const __nv_bfloat16* Ksm = Kb[cur];
            const __nv_bfloat16* Vsm = Vb[cur];

            // ---- S = Q @ K^T (16x64 per warp), bf16 mma ----
            float sacc[8][4];
            #pragma unroll
            for (int nt = 0; nt < 8; nt++)
                #pragma unroll
                for (int e = 0; e < 4; e++) sacc[nt][e] = 0.f;

            #pragma unroll
            for (int ks = 0; ks < 4; ks++) {
                #pragma unroll
                for (int nt = 0; nt < 8; nt++) {
                    uint32_t bb[2];
                    bb[0] = *(const uint32_t*)&Ksm[(nt*8+g)*AP + ks*16 + 2*q    ];
                    bb[1] = *(const uint32_t*)&Ksm[(nt*8+g)*AP + ks*16 + 2*q + 8];
                    mma_bf16(sacc[nt], qf[ks], bb);
                }
            }

            // ---- causal mask (partial tiles only) ----
            if (kb*64 + 63 > qbase + wrow) {
                const int r0 = qbase + wrow + g;
                const int r1 = r0 + 8;
                #pragma unroll
                for (int nt = 0; nt < 8; nt++) {
                    const int colg = kb*64 + nt*8 + 2*q;
                    if (colg     > r0) sacc[nt][0] = -1e30f;
                    if (colg + 1 > r0) sacc[nt][1] = -1e30f;
                    if (colg     > r1) sacc[nt][2] = -1e30f;
                    if (colg + 1 > r1) sacc[nt][3] = -1e30f;
                }
            }

            // ---- online softmax (fp32) ----
            float rm0 = -1e30f, rm1 = -1e30f;
            #pragma unroll
            for (int nt = 0; nt < 8; nt++) {
                rm0 = fmaxf(rm0, fmaxf(sacc[nt][0], sacc[nt][1]));
                rm1 = fmaxf(rm1, fmaxf(sacc[nt][2], sacc[nt][3]));
            }
            rm0 = fmaxf(rm0, __shfl_xor_sync(0xffffffffu, rm0, 1));
            rm0 = fmaxf(rm0, __shfl_xor_sync(0xffffffffu, rm0, 2));
            rm1 = fmaxf(rm1, __shfl_xor_sync(0xffffffffu, rm1, 1));
            rm1 = fmaxf(rm1, __shfl_xor_sync(0xffffffffu, rm1, 2));

            const float mn0 = fmaxf(m0, rm0);
            const float mn1 = fmaxf(m1, rm1);
            const float c0 = __expf(m0 - mn0);
            const float c1 = __expf(m1 - mn1);
            m0 = mn0; m1 = mn1;

            float s0 = 0.f, s1 = 0.f;
            #pragma unroll
            for (int nt = 0; nt < 8; nt++) {
                float p;
                p = __expf(sacc[nt][0] - mn0); s0 += p; sacc[nt][0] = p;
                p = __expf(sacc[nt][1] - mn0); s0 += p; sacc[nt][1] = p;
                p = __expf(sacc[nt][2] - mn1); s1 += p; sacc[nt][2] = p;
                p = __expf(sacc[nt][3] - mn1); s1 += p; sacc[nt][3] = p;
            }
            s0 += __shfl_xor_sync(0xffffffffu, s0, 1);
            s0 += __shfl_xor_sync(0xffffffffu, s0, 2);
            s1 += __shfl_xor_sync(0xffffffffu, s1, 1);
            s1 += __shfl_xor_sync(0xffffffffu, s1, 2);
            l0 = l0 * c0 + s0;
            l1 = l1 * c1 + s1;

            #pragma unroll
            for (int nt = 0; nt < 8; nt++) {
                oacc[nt][0] *= c0; oacc[nt][1] *= c0;
                oacc[nt][2] *= c1; oacc[nt][3] *= c1;
            }

            // ---- write P (bf16) ----
            #pragma unroll
            for (int nt = 0; nt < 8; nt++) {
                *(__nv_bfloat162*)&Ps[(wrow+g  )*AP + nt*8 + 2*q] =
                    __floats2bfloat162_rn(sacc[nt][0], sacc[nt][1]);
                *(__nv_bfloat162*)&Ps[(wrow+g+8)*AP + nt*8 + 2*q] =
                    __floats2bfloat162_rn(sacc[nt][2], sacc[nt][3]);
            }
            __syncwarp();

            // ---- O += P @ V (bf16 mma, Vt[d][key]) ----
            #pragma unroll
            for (int ks = 0; ks < 4; ks++) {
                uint32_t a[4];
                a[0] = *(const uint32_t*)&Ps[(wrow+g  )*AP + ks*16 + 2*q    ];
                a[1] = *(const uint32_t*)&Ps[(wrow+g+8)*AP + ks*16 + 2*q    ];
                a[2] = *(const uint32_t*)&Ps[(wrow+g  )*AP + ks*16 + 2*q + 8];
                a[3] = *(const uint32_t*)&Ps[(wrow+g+8)*AP + ks*16 + 2*q + 8];
                #pragma unroll
                for (int nt = 0; nt < 8; nt++) {
                    uint32_t bb[2];
                    bb[0] = *(const uint32_t*)&Vsm[(nt*8+g)*AP + ks*16 + 2*q    ];
                    bb[1] = *(const uint32_t*)&Vsm[(nt*8+g)*AP + ks*16 + 2*q + 8];
                    mma_bf16(oacc[nt], a, bb);
                }
            }
        }
        __syncthreads();
    }
    #undef ISSUE_TILE

    // ---- epilogue: normalize, tf32-round, write ctx (fp32) ----
    const float i0 = 1.f / l0;
    const float i1 = 1.f / l1;
    float* c0p = ctx + ((size_t)(b*SEQ + qbase + wrow + g    )) * DMODEL + h*DHEAD;
    float* c1p = ctx + ((size_t)(b*SEQ + qbase + wrow + g + 8)) * DMODEL + h*DHEAD;
    #pragma unroll
    for (int nt = 0; nt < 8; nt++) {
        *(float2*)(c0p + nt*8 + 2*q) =
            make_float2(f2tf32(oacc[nt][0]*i0), f2tf32(oacc[nt][1]*i0));
        *(float2*)(c1p + nt*8 + 2*q) =
            make_float2(f2tf32(oacc[nt][2]*i1), f2tf32(oacc[nt][3]*i1));
    }
}

// ---------------------------------------------------------------------------
// Row-wise LayerNorm. Optional tf32-rounded second output (FFN1 A operand).
// ---------------------------------------------------------------------------
__global__ __launch_bounds__(256)
void ln_kernel(const float* __restrict__ X, const float* __restrict__ g,
               const float* __restrict__ be, float* __restrict__ Y,
               float* __restrict__ Yr)
{
    __shared__ float red[8];
    const int row = blockIdx.x;
    const int tid = threadIdx.x;
    const float* x = X + (size_t)row * DMODEL;

    float v[3];
    float s = 0.f;
    #pragma unroll
    for (int i = 0; i < 3; i++) { v[i] = x[tid + i * 256]; s += v[i]; }

    #pragma unroll
    for (int off = 16; off; off >>= 1) s += __shfl_xor_sync(0xffffffffu, s, off);
    if ((tid & 31) == 0) red[tid >> 5] = s;
    __syncthreads();
    float total = 0.f;
    #pragma unroll
    for (int i = 0; i < 8; i++) total += red[i];
    const float mean = total * (1.0f / DMODEL);
    __syncthreads();

    float s2 = 0.f;
    #pragma unroll
    for (int i = 0; i < 3; i++) { const float d = v[i] - mean; s2 += d * d; }
    #pragma unroll
    for (int off = 16; off; off >>= 1) s2 += __shfl_xor_sync(0xffffffffu, s2, off);
    if ((tid & 31) == 0) red[tid >> 5] = s2;
    __syncthreads();
    float tot2 = 0.f;
    #pragma unroll
    for (int i = 0; i < 8; i++) tot2 += red[i];
    const float rstd = rsqrtf(tot2 * (1.0f / DMODEL) + EPS);

    #pragma unroll
    for (int i = 0; i < 3; i++) {
        const int c = tid + i * 256;
        const float y = (v[i] - mean) * rstd * g[c] + be[c];
        Y[(size_t)row * DMODEL + c] = y;
        if (Yr) Yr[(size_t)row * DMODEL + c] = f2tf32(y);
    }
}

// ---------------------------------------------------------------------------
// Launch
// ---------------------------------------------------------------------------
static void* sym_addr_raw(const void* sym)
{
    void* p = nullptr;
    cudaGetSymbolAddress(&p, sym);
    return p;
}

extern "C" void kernel_launch(void* const* d_in, const int* in_sizes, int n_in,
                              void* d_out, int out_size)
{
    const float* x   = (const float*)d_in[0];
    // d_in[1] = mask (causal; implied)
    const float* wq  = (const float*)d_in[2];
    const float* bq  = (const float*)d_in[3];
    const float* wk  = (const float*)d_in[4];
    const float* bk  = (const float*)d_in[5];
    const float* wv  = (const float*)d_in[6];
    const float* bv  = (const float*)d_in[7];
    const float* wo  = (const float*)d_in[8];
    const float* bo  = (const float*)d_in[9];
    const float* g1  = (const float*)d_in[10];
    const float* be1 = (const float*)d_in[11];
    const float* w1  = (const float*)d_in[12];
    const float* b1  = (const float*)d_in[13];
    const float* w2  = (const float*)d_in[14];
    const float* b2  = (const float*)d_in[15];
    const float* g2  = (const float*)d_in[16];
    const float* be2 = (const float*)d_in[17];
    float* out = (float*)d_out;

    __nv_bfloat16* qb = (__nv_bfloat16*)sym_addr_raw(g_qb);
    __nv_bfloat16* kb = (__nv_bfloat16*)sym_addr_raw(g_kb);
    __nv_bfloat16* vb = (__nv_bfloat16*)sym_addr_raw(g_vb);
    __nv_bfloat16* vT = (__nv_bfloat16*)sym_addr_raw(g_vT);
    float* ctx  = (float*)sym_addr_raw(g_ctx);
    float* t1   = (float*)sym_addr_raw(g_t1);
    float* hh   = (float*)sym_addr_raw(g_h);
    float* hr   = (float*)sym_addr_raw(g_hr);
    float* f1   = (float*)sym_addr_raw(g_f1);
    float* t2   = (float*)sym_addr_raw(g_t2);
    float* xr   = (float*)sym_addr_raw(g_xr);
    float* wqkv = (float*)sym_addr_raw(g_wqkv);
    float* bqkv = (float*)sym_addr_raw(g_bqkv);
    float* wor  = (float*)sym_addr_raw(g_wor);
    float* w1r  = (float*)sym_addr_raw(g_w1r);
    float* w2r  = (float*)sym_addr_raw(g_w2r);

    cudaFuncSetAttribute(attn_bf, cudaFuncAttributeMaxDynamicSharedMemorySize,
                         ATTN_SMEM);
    cudaFuncSetAttribute(gemm_ca<EP_QKV, 128>,
                         cudaFuncAttributeMaxDynamicSharedMemorySize, GEMM_SMEM_BM(128));
    cudaFuncSetAttribute(gemm_ca<EP_RESID, 64>,
                         cudaFuncAttributeMaxDynamicSharedMemorySize, GEMM_SMEM_BM(64));
    cudaFuncSetAttribute(gemm_ca<EP_GELU_TF32, 64>,
                         cudaFuncAttributeMaxDynamicSharedMemorySize, GEMM_SMEM_BM(64));

    // 0. prep (tf32 operands, packed QKV)
    const int nX = MROWS * DMODEL / 4;
    const int nW = DMODEL * DMODEL / 4;
    const int nW1 = DMODEL * DFF / 4;
    round_tf32_kernel<<<(nX + 255)/256, 256>>>(x, xr, nX);
    round_pack_kernel<<<(nW + 255)/256, 256>>>(wq, wqkv, 0);
    round_pack_kernel<<<(nW + 255)/256, 256>>>(wk, wqkv, DMODEL);
    round_pack_kernel<<<(nW + 255)/256, 256>>>(wv, wqkv, 2*DMODEL);
    pack_bias_kernel<<<3, 256>>>(bq, bqkv, 0);
    pack_bias_kernel<<<3, 256>>>(bk, bqkv, DMODEL);
    pack_bias_kernel<<<3, 256>>>(bv, bqkv, 2*DMODEL);
    round_tf32_kernel<<<(nW  + 255)/256, 256>>>(wo, wor, nW);
    round_tf32_kernel<<<(nW1 + 255)/256, 256>>>(w1, w1r, nW1);
    round_tf32_kernel<<<(nW1 + 255)/256, 256>>>(w2, w2r, nW1);

    // 1. Fused QKV projection (tf32) -> q/k/v bf16 (q pre-scaled 1/8)
    gemm_ca<EP_QKV, 128><<<dim3(NQKV/128, MROWS/128), 256, GEMM_SMEM_BM(128)>>>(
        xr, wqkv, bqkv, nullptr, nullptr, NQKV, DMODEL);

    // 1b. transpose V -> vT [b][h*d][s]
    transposeV_kernel<<<dim3(SEQ/32, DMODEL/32, BATCH), dim3(32, 8)>>>(vb, vT);

    // 2. Causal flash attention (bf16 mma, fp32 softmax) -> ctx
    attn_bf<<<dim3(SEQ/128, BATCH*NHEAD), 256, ATTN_SMEM>>>(qb, kb, vT, ctx);

    // 3. ctx @ wo + bo + x -> t1 (tf32)
    gemm_ca<EP_RESID, 64><<<dim3(DMODEL/128, MROWS/64), 256, GEMM_SMEM_BM(64)>>>(
        ctx, wor, bo, x, t1, DMODEL, DMODEL);

    // 4. LN1 -> h (fp32) + hr (tf32)
    ln_kernel<<<MROWS, 256>>>(t1, g1, be1, hh, hr);

    // 5. GELU(hr @ w1 + b1) -> f1 (tf32)
    gemm_ca<EP_GELU_TF32, 64><<<dim3(DFF/128, MROWS/64), 256, GEMM_SMEM_BM(64)>>>(
        hr, w1r, b1, nullptr, f1, DFF, DMODEL);

    // 6. f1 @ w2 + b2 + h -> t2 (tf32)
    gemm_ca<EP_RESID, 64><<<dim3(DMODEL/128, MROWS/64), 256, GEMM_SMEM_BM(64)>>>(
        f1, w2r, b2, hh, t2, DMODEL, DFF);

    // 7. LN2 -> out
    ln_kernel<<<MROWS, 256>>>(t2, g2, be2, out, nullptr);
}

// round 15
// speedup vs baseline: 1.4331x; 1.1121x over previous
#include <cuda_runtime.h>
#include <cuda_bf16.h>
#include <math.h>
#include <stdint.h>

// Problem constants
#define BATCH 4
#define SEQ   2048
#define DMODEL 768
#define NHEAD 12
#define DHEAD 64
#define DFF   3072
#define MROWS (BATCH*SEQ)          // 8192
#define NQKV  (3*DMODEL)           // 2304
#define EPS   1e-5f

// ---------------------------------------------------------------------------
// Scratch (device globals; allocation-free contract)
// ---------------------------------------------------------------------------
__device__ __nv_bfloat16 g_qb [(size_t)MROWS * DMODEL];   // bf16, pre-scaled 1/8
__device__ __nv_bfloat16 g_kb [(size_t)MROWS * DMODEL];
__device__ __nv_bfloat16 g_vb [(size_t)MROWS * DMODEL];   // [b,s,h*d]
__device__ __nv_bfloat16 g_vT [(size_t)MROWS * DMODEL];   // [b][h*d][s]
__device__ __nv_bfloat16 g_ctxb[(size_t)MROWS * DMODEL];  // attn out (WO A operand)
__device__ float g_t1 [(size_t)MROWS * DMODEL];
__device__ float g_h  [(size_t)MROWS * DMODEL];   // full fp32 (residual)
__device__ float g_hr [(size_t)MROWS * DMODEL];   // tf32 (FFN1 A operand)
__device__ float g_f1 [(size_t)MROWS * DFF];      // tf32 (FFN2 A operand)
__device__ float g_t2 [(size_t)MROWS * DMODEL];
// operands
__device__ __nv_bfloat16 g_xb   [(size_t)MROWS * DMODEL];
__device__ __nv_bfloat16 g_wqkvT[(size_t)NQKV * DMODEL];  // [2304][768] bf16
__device__ float         g_bqkv [NQKV];
__device__ __nv_bfloat16 g_woT  [(size_t)DMODEL * DMODEL];// [768][768] bf16
__device__ float g_w1r [(size_t)DMODEL * DFF];    // tf32
__device__ float g_w2r [(size_t)DFF * DMODEL];    // tf32

// ---------------------------------------------------------------------------
// helpers
// ---------------------------------------------------------------------------
__device__ __forceinline__ float f2tf32(float x)
{
    uint32_t u;
    asm("cvt.rna.tf32.f32 %0, %1;" : "=r"(u) : "f"(x));
    return __uint_as_float(u);
}

__device__ __forceinline__ void mma_tf32(float* c, const uint32_t* a, const uint32_t* b)
{
    asm volatile(
        "mma.sync.aligned.m16n8k8.row.col.f32.tf32.tf32.f32 "
        "{%0,%1,%2,%3},{%4,%5,%6,%7},{%8,%9},{%0,%1,%2,%3};\n"
        : "+f"(c[0]), "+f"(c[1]), "+f"(c[2]), "+f"(c[3])
        : "r"(a[0]), "r"(a[1]), "r"(a[2]), "r"(a[3]), "r"(b[0]), "r"(b[1]));
}

__device__ __forceinline__ void mma_bf16(float* c, const uint32_t* a, const uint32_t* b)
{
    asm volatile(
        "mma.sync.aligned.m16n8k16.row.col.f32.bf16.bf16.f32 "
        "{%0,%1,%2,%3},{%4,%5,%6,%7},{%8,%9},{%0,%1,%2,%3};\n"
        : "+f"(c[0]), "+f"(c[1]), "+f"(c[2]), "+f"(c[3])
        : "r"(a[0]), "r"(a[1]), "r"(a[2]), "r"(a[3]), "r"(b[0]), "r"(b[1]));
}

__device__ __forceinline__ uint32_t smem_u32(const void* p)
{
    return (uint32_t)__cvta_generic_to_shared(p);
}

#define CPA16(dst, src) \
    asm volatile("cp.async.cg.shared.global [%0], [%1], 16;\n" :: "r"(dst), "l"(src))
#define CPA_COMMIT() asm volatile("cp.async.commit_group;\n")
#define CPA_WAIT1()  asm volatile("cp.async.wait_group 1;\n")
#define CPA_WAIT0()  asm volatile("cp.async.wait_group 0;\n")

// ---------------------------------------------------------------------------
// Prep kernels
// ---------------------------------------------------------------------------
__global__ __launch_bounds__(256)
void round_tf32_kernel(const float* __restrict__ src, float* __restrict__ dst, int n4)
{
    const int i = blockIdx.x * blockDim.x + threadIdx.x;
    if (i < n4) {
        float4 v = *((const float4*)src + i);
        v.x = f2tf32(v.x); v.y = f2tf32(v.y);
        v.z = f2tf32(v.z); v.w = f2tf32(v.w);
        *((float4*)dst + i) = v;
    }
}

__global__ __launch_bounds__(256)
void cvt_bf16_kernel(const float* __restrict__ src, __nv_bfloat16* __restrict__ dst, int n4)
{
    const int i = blockIdx.x * blockDim.x + threadIdx.x;
    if (i < n4) {
        float4 v = *((const float4*)src + i);
        *(__nv_bfloat162*)(dst + (size_t)i*4)     = __floats2bfloat162_rn(v.x, v.y);
        *(__nv_bfloat162*)(dst + (size_t)i*4 + 2) = __floats2bfloat162_rn(v.z, v.w);
    }
}

// src [K][N] fp32 -> dst rows (off+n) of [*][K] bf16 (transpose + convert)
__global__ __launch_bounds__(256)
void packT_bf16_kernel(const float* __restrict__ src, __nv_bfloat16* __restrict__ dst,
                       int K, int N, int off)
{
    __shared__ float t[32][33];
    const int k0 = blockIdx.x * 32;
    const int n0 = blockIdx.y * 32;
    const int x = threadIdx.x;
    const int y = threadIdx.y;
    #pragma unroll
    for (int i = 0; i < 32; i += 8)
        t[y + i][x] = src[(size_t)(k0 + y + i) * N + n0 + x];
    __syncthreads();
    #pragma unroll
    for (int i = 0; i < 32; i += 8)
        dst[(size_t)(off + n0 + y + i) * K + k0 + x] = __float2bfloat16_rn(t[x][y + i]);
}

__global__ __launch_bounds__(256)
void pack_bias_kernel(const float* __restrict__ src, float* __restrict__ dst, int off)
{
    const int i = blockIdx.x * blockDim.x + threadIdx.x;
    if (i < DMODEL) dst[off + i] = src[i];
}

// V [b,s,768] bf16 -> vT [b][768][2048] bf16
__global__ __launch_bounds__(256)
void transposeV_kernel(const __nv_bfloat16* __restrict__ src,
                       __nv_bfloat16* __restrict__ dst)
{
    __shared__ __nv_bfloat16 t[32][33];
    const int s0 = blockIdx.x * 32;
    const int c0 = blockIdx.y * 32;
    const int b  = blockIdx.z;
    const int x = threadIdx.x;
    const int y = threadIdx.y;
    #pragma unroll
    for (int i = 0; i < 32; i += 8)
        t[y + i][x] = src[((size_t)(b*SEQ + s0 + y + i)) * DMODEL + c0 + x];
    __syncthreads();
    #pragma unroll
    for (int i = 0; i < 32; i += 8)
        dst[((size_t)(b*DMODEL + c0 + y + i)) * SEQ + s0 + x] = t[x][y + i];
}

enum { EP_RESID = 1, EP_GELU_TF32 = 2, EP_QKV = 4 };

// ---------------------------------------------------------------------------
// tf32 cp.async GEMM (verified R11): C = A[M,K] @ B[K,N] + bias (+epilogue).
// BM=64; BN=128, BK=16, 256 threads, warp tile 32x32.
// A smem [m][k] pitch 20; B smem [k][n] pitch 136.
// ---------------------------------------------------------------------------
#define APITCH 20
#define BPITCH 136
#define BBUF   (16*BPITCH)
#define GEMM_SMEM_BM(BM) ((3*((BM)*APITCH) + 3*BBUF) * 4)

template<int EPI, int BM>
__global__ __launch_bounds__(256)
void gemm_ca(const float* __restrict__ A, const float* __restrict__ Bm,
             const float* __restrict__ bias, const float* __restrict__ resid,
             float* __restrict__ C, int Ndim, int Kdim)
{
    constexpr int WROWS = BM / 2;
    constexpr int MT    = WROWS / 16;
    constexpr int ABUFT = BM * APITCH;

    extern __shared__ float gsm[];
    float* As = gsm;
    float* Bs = gsm + 3*ABUFT;

    const int tid  = threadIdx.x;
    const int lane = tid & 31;
    const int warp = tid >> 5;
    const int wm = warp & 1;
    const int wn = warp >> 1;
    const int g = lane >> 2;
    const int q = lane & 3;
    const int row0 = blockIdx.y * BM;
    const int col0 = blockIdx.x * 128;

    const int br = tid >> 4;
    const int bc8 = (tid & 15) * 8;

    const uint32_t asu = smem_u32(As);
    const uint32_t bsu = smem_u32(Bs);

    float acc[MT][4][4];
    #pragma unroll
    for (int i = 0; i < MT; i++)
        #pragma unroll
        for (int j = 0; j < 4; j++)
            #pragma unroll
            for (int r = 0; r < 4; r++) acc[i][j][r] = 0.f;

    const int nk = Kdim >> 4;

    #define GISSUE(i, bf_) do {                                                     \
        const int k0_ = (i) << 4;                                                   \
        if (BM == 128) {                                                            \
            const int ar  = tid >> 1;                                               \
            const int ac8 = (tid & 1) * 8;                                          \
            const float* asrc = A + (size_t)(row0 + ar) * Kdim + k0_ + ac8;         \
            const uint32_t ad = asu + (uint32_t)((bf_)*ABUFT + ar*APITCH + ac8)*4u; \
            CPA16(ad,       asrc);                                                  \
            CPA16(ad + 16u, asrc + 4);                                              \
        } else {                                                                    \
            const int ar  = tid >> 2;                                               \
            const int ac4 = (tid & 3) * 4;                                          \
            const float* asrc = A + (size_t)(row0 + ar) * Kdim + k0_ + ac4;         \
            const uint32_t ad = asu + (uint32_t)((bf_)*ABUFT + ar*APITCH + ac4)*4u; \
            CPA16(ad, asrc);                                                        \
        }                                                                           \
        const float* bsrc = Bm + (size_t)(k0_ + br) * Ndim + col0 + bc8;            \
        const uint32_t bd = bsu + (uint32_t)((bf_)*BBUF + br*BPITCH + bc8) * 4u;    \
        CPA16(bd,       bsrc);                                                      \
        CPA16(bd + 16u, bsrc + 4);                                                  \
        CPA_COMMIT();                                                               \
    } while (0)

    #define GCOMPUTE(bf_) do {                                                    \
        const float* Ab = As + (bf_)*ABUFT;                                       \
        const float* Bb = Bs + (bf_)*BBUF;                                        \
        _Pragma("unroll")                                                         \
        for (int ks = 0; ks < 16; ks += 8) {                                      \
            uint32_t af[MT][4], bf2[4][2];                                        \
            _Pragma("unroll")                                                     \
            for (int mt = 0; mt < MT; mt++) {                                     \
                const int m0 = wm*WROWS + mt*16;                                  \
                af[mt][0] = __float_as_uint(Ab[(m0+g  )*APITCH + ks+q  ]);        \
                af[mt][1] = __float_as_uint(Ab[(m0+g+8)*APITCH + ks+q  ]);        \
                af[mt][2] = __float_as_uint(Ab[(m0+g  )*APITCH + ks+q+4]);        \
                af[mt][3] = __float_as_uint(Ab[(m0+g+8)*APITCH + ks+q+4]);        \
            }                                                                     \
            _Pragma("unroll")                                                     \
            for (int nt = 0; nt < 4; nt++) {                                      \
                const int n0 = wn*32 + nt*8;                                      \
                bf2[nt][0] = __float_as_uint(Bb[(ks+q  )*BPITCH + n0+g]);         \
                bf2[nt][1] = __float_as_uint(Bb[(ks+q+4)*BPITCH + n0+g]);         \
            }                                                                     \
            _Pragma("unroll")                                                     \
            for (int mt = 0; mt < MT; mt++)                                       \
                _Pragma("unroll")                                                 \
                for (int nt = 0; nt < 4; nt++)                                    \
                    mma_tf32(acc[mt][nt], af[mt], bf2[nt]);                       \
        }                                                                         \
    } while (0)

    GISSUE(0, 0);
    GISSUE(1, 1);

    for (int i = 0; i < nk; i++) {
        if (i + 1 < nk) { CPA_WAIT1(); } else { CPA_WAIT0(); }
        __syncthreads();
        const int cb = i % 3;
        GCOMPUTE(cb);
        if (i + 2 < nk) GISSUE(i + 2, (i + 2) % 3);
        __syncthreads();
    }

    #undef GISSUE
    #undef GCOMPUTE

    #pragma unroll
    for (int mt = 0; mt < MT; mt++) {
        const int mlo = row0 + wm*WROWS + mt*16 + g;
        #pragma unroll
        for (int nt = 0; nt < 4; nt++) {
            const int n = col0 + wn*32 + nt*8 + 2*q;
            const float b0 = bias[n], b1 = bias[n+1];
            #pragma unroll
            for (int half = 0; half < 2; half++) {
                const int m = mlo + half*8;
                float v0 = acc[mt][nt][half*2+0] + b0;
                float v1 = acc[mt][nt][half*2+1] + b1;
                if (EPI == EP_RESID) {
                    v0 += resid[(size_t)m * Ndim + n];
                    v1 += resid[(size_t)m * Ndim + n + 1];
                    *(float2*)(C + (size_t)m * Ndim + n) = make_float2(v0, v1);
                }
                if (EPI == EP_GELU_TF32) {
                    v0 = f2tf32(0.5f * v0 * (1.0f + erff(v0 * 0.70710678118654752f)));
                    v1 = f2tf32(0.5f * v1 * (1.0f + erff(v1 * 0.70710678118654752f)));
                    *(float2*)(C + (size_t)m * Ndim + n) = make_float2(v0, v1);
                }
            }
        }
    }
}

// ---------------------------------------------------------------------------
// bf16 cp.async GEMM (validated R12/R13): C = A(bf16) @ BT(bf16 [N][K])^T.
// BM in {128,64}, BN=128, BK=32, 256 threads, warp tile (BM/2)x32.
// smem: A [BM][KP], BT [128][KP] halves, KP=40.
// EP_QKV scatters bf16 q/k/v; EP_RESID writes fp32 with fp32 residual.
// ---------------------------------------------------------------------------
#define KP 40
#define BF_SMEM_BM(BM) ((3*((BM)*KP) + 3*(128*KP)) * 2)

template<int EPI, int BM>
__global__ __launch_bounds__(256)
void gemm_bf(const __nv_bfloat16* __restrict__ A, const __nv_bfloat16* __restrict__ BT,
             const float* __restrict__ bias, const float* __restrict__ resid,
             float* __restrict__ Cf, int Ndim, int Kdim)
{
    constexpr int WROWS = BM / 2;
    constexpr int MT    = WROWS / 16;
    constexpr int ABUFT = BM * KP;
    constexpr int BBUFT = 128 * KP;

    extern __shared__ __align__(16) char gsmraw[];
    __nv_bfloat16* As = (__nv_bfloat16*)gsmraw;
    __nv_bfloat16* Bs = As + 3*ABUFT;

    const int tid  = threadIdx.x;
    const int lane = tid & 31;
    const int warp = tid >> 5;
    const int wm = warp & 1;
    const int wn = warp >> 1;
    const int g = lane >> 2;
    const int q = lane & 3;
    const int row0 = blockIdx.y * BM;
    const int col0 = blockIdx.x * 128;

    const uint32_t asu = smem_u32(As);
    const uint32_t bsu = smem_u32(Bs);

    float acc[MT][4][4];
    #pragma unroll
    for (int i = 0; i < MT; i++)
        #pragma unroll
        for (int j = 0; j < 4; j++)
            #pragma unroll
            for (int r = 0; r < 4; r++) acc[i][j][r] = 0.f;

    const int nk = Kdim >> 5;

    #define GISSUE(i, bf_) do {                                                       \
        const int k0_ = (i) << 5;                                                     \
        if (BM == 128) {                                                              \
            const int ar = tid >> 1;                                                  \
            const int ac = (tid & 1) * 16;                                            \
            const __nv_bfloat16* asrc = A + (size_t)(row0 + ar) * Kdim + k0_ + ac;    \
            const uint32_t ad = asu + (uint32_t)((bf_)*ABUFT + ar*KP + ac) * 2u;      \
            CPA16(ad,       asrc);                                                    \
            CPA16(ad + 16u, asrc + 8);                                                \
        } else {                                                                      \
            const int ar = tid >> 2;                                                  \
            const int ac = (tid & 3) * 8;                                             \
            const __nv_bfloat16* asrc = A + (size_t)(row0 + ar) * Kdim + k0_ + ac;    \
            const uint32_t ad = asu + (uint32_t)((bf_)*ABUFT + ar*KP + ac) * 2u;      \
            CPA16(ad, asrc);                                                          \
        }                                                                             \
        {                                                                             \
            const int br = tid >> 1;                                                  \
            const int bc = (tid & 1) * 16;                                            \
            const __nv_bfloat16* bsrc = BT + (size_t)(col0 + br) * Kdim + k0_ + bc;   \
            const uint32_t bd = bsu + (uint32_t)((bf_)*BBUFT + br*KP + bc) * 2u;      \
            CPA16(bd,       bsrc);                                                    \
            CPA16(bd + 16u, bsrc + 8);                                                \
        }                                                                             \
        CPA_COMMIT();                                                                 \
    } while (0)

    #define GCOMPUTE(bf_) do {                                                        \
        const __nv_bfloat16* Ab = As + (bf_)*ABUFT;                                   \
        const __nv_bfloat16* Bb = Bs + (bf_)*BBUFT;                                   \
        _Pragma("unroll")                                                             \
        for (int ks = 0; ks < 32; ks += 16) {                                         \
            uint32_t af[MT][4], bf2[4][2];                                            \
            _Pragma("unroll")                                                         \
            for (int mt = 0; mt < MT; mt++) {                                         \
                const int m0 = wm*WROWS + mt*16;                                      \
                af[mt][0] = *(const uint32_t*)&Ab[(m0+g  )*KP + ks + 2*q    ];        \
                af[mt][1] = *(const uint32_t*)&Ab[(m0+g+8)*KP + ks + 2*q    ];        \
                af[mt][2] = *(const uint32_t*)&Ab[(m0+g  )*KP + ks + 2*q + 8];        \
                af[mt][3] = *(const uint32_t*)&Ab[(m0+g+8)*KP + ks + 2*q + 8];        \
            }                                                                         \
            _Pragma("unroll")                                                         \
            for (int nt = 0; nt < 4; nt++) {                                          \
                const int n0 = wn*32 + nt*8;                                          \
                bf2[nt][0] = *(const uint32_t*)&Bb[(n0+g)*KP + ks + 2*q    ];         \
                bf2[nt][1] = *(const uint32_t*)&Bb[(n0+g)*KP + ks + 2*q + 8];         \
            }                                                                         \
            _Pragma("unroll")                                                         \
            for (int mt = 0; mt < MT; mt++)                                           \
                _Pragma("unroll")                                                     \
                for (int nt = 0; nt < 4; nt++)                                        \
                    mma_bf16(acc[mt][nt], af[mt], bf2[nt]);                           \
        }                                                                             \
    } while (0)

    GISSUE(0, 0);
    GISSUE(1, 1);

    for (int i = 0; i < nk; i++) {
        if (i + 1 < nk) { CPA_WAIT1(); } else { CPA_WAIT0(); }
        __syncthreads();
        const int cb = i % 3;
        GCOMPUTE(cb);
        if (i + 2 < nk) GISSUE(i + 2, (i + 2) % 3);
        __syncthreads();
    }

    #undef GISSUE
    #undef GCOMPUTE

    #pragma unroll
    for (int mt = 0; mt < MT; mt++) {
        const int mlo = row0 + wm*WROWS + mt*16 + g;
        #pragma unroll
        for (int nt = 0; nt < 4; nt++) {
            const int n = col0 + wn*32 + nt*8 + 2*q;
            const float b0 = bias[n], b1 = bias[n+1];
            #pragma unroll
            for (int half = 0; half < 2; half++) {
                const int m = mlo + half*8;
                float v0 = acc[mt][nt][half*2+0] + b0;
                float v1 = acc[mt][nt][half*2+1] + b1;
                if (EPI == EP_RESID) {
                    v0 += resid[(size_t)m * Ndim + n];
                    v1 += resid[(size_t)m * Ndim + n + 1];
                    *(float2*)(Cf + (size_t)m * Ndim + n) = make_float2(v0, v1);
                }
                if (EPI == EP_QKV) {
                    __nv_bfloat16* dst;
                    int nc;
                    float sc;
                    if (n < DMODEL)        { dst = g_qb; nc = n;            sc = 0.125f; }
                    else if (n < 2*DMODEL) { dst = g_kb; nc = n -   DMODEL; sc = 1.0f;   }
                    else                   { dst = g_vb; nc = n - 2*DMODEL; sc = 1.0f;   }
                    *(__nv_bfloat162*)(dst + (size_t)m * DMODEL + nc) =
                        __floats2bfloat162_rn(v0 * sc, v1 * sc);
                }
            }
        }
    }
}

// ---------------------------------------------------------------------------
// Tensor-core flash attention (causal, bf16 mma, fp32 softmax). Verified R14.
// ctx output now bf16 (WO GEMM A operand).
// ---------------------------------------------------------------------------
#define AP 72
#define ATTN_SMEM ((2*64*AP + 2*64*AP + 128*AP) * 2)   // 55296 B

__global__ __launch_bounds__(256, 2)
void attn_bf(const __nv_bfloat16* __restrict__ Q, const __nv_bfloat16* __restrict__ K,
             const __nv_bfloat16* __restrict__ Vt, __nv_bfloat16* __restrict__ ctx)
{
    extern __shared__ __align__(16) char smraw[];
    __nv_bfloat16* sm = (__nv_bfloat16*)smraw;
    __nv_bfloat16* Kb[2] = { sm,            sm + 64*AP };
    __nv_bfloat16* Vb[2] = { sm + 2*64*AP,  sm + 3*64*AP };
    __nv_bfloat16* Ps    = sm + 4*64*AP;

    const int bh = blockIdx.y;
    const int b  = bh / NHEAD;
    const int h  = bh % NHEAD;
    const int qt = (SEQ/128 - 1) - blockIdx.x;
    const int tid  = threadIdx.x;
    const int warp = tid >> 5;
    const int lane = tid & 31;
    const int g = lane >> 2;
    const int q = lane & 3;
    const int wrow = warp * 16;
    const int qbase = qt * 128;

    const int lr = tid >> 2;
    const int cb = (tid & 3) * 16;

    const uint32_t kbu[2] = { smem_u32(Kb[0]), smem_u32(Kb[1]) };
    const uint32_t vbu[2] = { smem_u32(Vb[0]), smem_u32(Vb[1]) };

    #define ISSUE_TILE(kb, sel) do {                                                        \
        const __nv_bfloat16* ksrc =                                                         \
            K  + ((size_t)(b*SEQ + (kb)*64 + lr))*DMODEL + h*DHEAD + cb;                    \
        const __nv_bfloat16* vsrc =                                                         \
            Vt + ((size_t)(b*DMODEL + h*DHEAD + lr))*SEQ + (kb)*64 + cb;                    \
        const uint32_t kd = kbu[sel] + (uint32_t)(lr*AP + cb) * 2u;                         \
        const uint32_t vd = vbu[sel] + (uint32_t)(lr*AP + cb) * 2u;                         \
        CPA16(kd,       ksrc);                                                              \
        CPA16(kd + 16u, ksrc + 8);                                                          \
        CPA16(vd,       vsrc);                                                              \
        CPA16(vd + 16u, vsrc + 8);                                                          \
        CPA_COMMIT();                                                                       \
    } while (0)

    ISSUE_TILE(0, 0);

    {
        const int qlr = tid >> 1;
        const int qlc = (tid & 1) * 32;
        const __nv_bfloat16* qsrc =
            Q + ((size_t)(b*SEQ + qbase + qlr))*DMODEL + h*DHEAD + qlc;
        #pragma unroll
        for (int i = 0; i < 4; i++)
            *(uint4*)&Ps[qlr*AP + qlc + i*8] = *(const uint4*)(qsrc + i*8);
    }
    __syncthreads();
    uint32_t qf[4][4];
    #pragma unroll
    for (int ks = 0; ks < 4; ks++) {
        qf[ks][0] = *(const uint32_t*)&Ps[(wrow+g  )*AP + ks*16 + 2*q    ];
        qf[ks][1] = *(const uint32_t*)&Ps[(wrow+g+8)*AP + ks*16 + 2*q    ];
        qf[ks][2] = *(const uint32_t*)&Ps[(wrow+g  )*AP + ks*16 + 2*q + 8];
        qf[ks][3] = *(const uint32_t*)&Ps[(wrow+g+8)*AP + ks*16 + 2*q + 8];
    }
    __syncthreads();

    float oacc[8][4];
    #pragma unroll
    for (int nt = 0; nt < 8; nt++)
        #pragma unroll
        for (int e = 0; e < 4; e++) oacc[nt][e] = 0.f;
    float m0 = -1e30f, m1 = -1e30f, l0 = 0.f, l1 = 0.f;

    const int nkb = 2*qt + 2;

    for (int kb = 0; kb < nkb; kb++) {
        const int cur = kb & 1;
        if (kb + 1 < nkb) {
            ISSUE_TILE(kb + 1, cur ^ 1);
            CPA_WAIT1();
        } else {
            CPA_WAIT0();
        }
        __syncthreads();

        const bool skip = (kb*64) > (qbase + wrow + 15);
        if (!skip) {
            const __nv_bfloat16* Ksm = Kb[cur];
            const __nv_bfloat16* Vsm = Vb[cur];

            float sacc[8][4];
            #pragma unroll
            for (int nt = 0; nt < 8; nt++)
                #pragma unroll
                for (int e = 0; e < 4; e++) sacc[nt][e] = 0.f;

            #pragma unroll
            for (int ks = 0; ks < 4; ks++) {
                #pragma unroll
                for (int nt = 0; nt < 8; nt++) {
                    uint32_t bb[2];
                    bb[0] = *(const uint32_t*)&Ksm[(nt*8+g)*AP + ks*16 + 2*q    ];
                    bb[1] = *(const uint32_t*)&Ksm[(nt*8+g)*AP + ks*16 + 2*q + 8];
                    mma_bf16(sacc[nt], qf[ks], bb);
                }
            }

            if (kb*64 + 63 > qbase + wrow) {
                const int r0 = qbase + wrow + g;
                const int r1 = r0 + 8;
                #pragma unroll
                for (int nt = 0; nt < 8; nt++) {
                    const int colg = kb*64 + nt*8 + 2*q;
                    if (colg     > r0) sacc[nt][0] = -1e30f;
                    if (colg + 1 > r0) sacc[nt][1] = -1e30f;
                    if (colg     > r1) sacc[nt][2] = -1e30f;
                    if (colg + 1 > r1) sacc[nt][3] = -1e30f;
                }
            }

            float rm0 = -1e30f, rm1 = -1e30f;
            #pragma unroll
            for (int nt = 0; nt < 8; nt++) {
                rm0 = fmaxf(rm0, fmaxf(sacc[nt][0], sacc[nt][1]));
                rm1 = fmaxf(rm1, fmaxf(sacc[nt][2], sacc[nt][3]));
            }
            rm0 = fmaxf(rm0, __shfl_xor_sync(0xffffffffu, rm0, 1));
            rm0 = fmaxf(rm0, __shfl_xor_sync(0xffffffffu, rm0, 2));
            rm1 = fmaxf(rm1, __shfl_xor_sync(0xffffffffu, rm1, 1));
            rm1 = fmaxf(rm1, __shfl_xor_sync(0xffffffffu, rm1, 2));

            const float mn0 = fmaxf(m0, rm0);
            const float mn1 = fmaxf(m1, rm1);
            const float c0 = __expf(m0 - mn0);
            const float c1 = __expf(m1 - mn1);
            m0 = mn0; m1 = mn1;

            float s0 = 0.f, s1 = 0.f;
            #pragma unroll
            for (int nt = 0; nt < 8; nt++) {
                float p;
                p = __expf(sacc[nt][0] - mn0); s0 += p; sacc[nt][0] = p;
                p = __expf(sacc[nt][1] - mn0); s0 += p; sacc[nt][1] = p;
                p = __expf(sacc[nt][2] - mn1); s1 += p; sacc[nt][2] = p;
                p = __expf(sacc[nt][3] - mn1); s1 += p; sacc[nt][3] = p;
            }
            s0 += __shfl_xor_sync(0xffffffffu, s0, 1);
            s0 += __shfl_xor_sync(0xffffffffu, s0, 2);
            s1 += __shfl_xor_sync(0xffffffffu, s1, 1);
            s1 += __shfl_xor_sync(0xffffffffu, s1, 2);
            l0 = l0 * c0 + s0;
            l1 = l1 * c1 + s1;

            #pragma unroll
            for (int nt = 0; nt < 8; nt++) {
                oacc[nt][0] *= c0; oacc[nt][1] *= c0;
                oacc[nt][2] *= c1; oacc[nt][3] *= c1;
            }

            #pragma unroll
            for (int nt = 0; nt < 8; nt++) {
                *(__nv_bfloat162*)&Ps[(wrow+g  )*AP + nt*8 + 2*q] =
                    __floats2bfloat162_rn(sacc[nt][0], sacc[nt][1]);
                *(__nv_bfloat162*)&Ps[(wrow+g+8)*AP + nt*8 + 2*q] =
                    __floats2bfloat162_rn(sacc[nt][2], sacc[nt][3]);
            }
            __syncwarp();

            #pragma unroll
            for (int ks = 0; ks < 4; ks++) {
                uint32_t a[4];
                a[0] = *(const uint32_t*)&Ps[(wrow+g  )*AP + ks*16 + 2*q    ];
                a[1] = *(const uint32_t*)&Ps[(wrow+g+8)*AP + ks*16 + 2*q    ];
                a[2] = *(const uint32_t*)&Ps[(wrow+g  )*AP + ks*16 + 2*q + 8];
                a[3] = *(const uint32_t*)&Ps[(wrow+g+8)*AP + ks*16 + 2*q + 8];
                #pragma unroll
                for (int nt = 0; nt < 8; nt++) {
                    uint32_t bb[2];
                    bb[0] = *(const uint32_t*)&Vsm[(nt*8+g)*AP + ks*16 + 2*q    ];
                    bb[1] = *(const uint32_t*)&Vsm[(nt*8+g)*AP + ks*16 + 2*q + 8];
                    mma_bf16(oacc[nt], a, bb);
                }
            }
        }
        __syncthreads();
    }
    #undef ISSUE_TILE

    const float i0 = 1.f / l0;
    const float i1 = 1.f / l1;
    __nv_bfloat16* c0p = ctx + ((size_t)(b*SEQ + qbase + wrow + g    )) * DMODEL + h*DHEAD;
    __nv_bfloat16* c1p = ctx + ((size_t)(b*SEQ + qbase + wrow + g + 8)) * DMODEL + h*DHEAD;
    #pragma unroll
    for (int nt = 0; nt < 8; nt++) {
        *(__nv_bfloat162*)(c0p + nt*8 + 2*q) =
            __floats2bfloat162_rn(oacc[nt][0]*i0, oacc[nt][1]*i0);
        *(__nv_bfloat162*)(c1p + nt*8 + 2*q) =
            __floats2bfloat162_rn(oacc[nt][2]*i1, oacc[nt][3]*i1);
    }
}

// ---------------------------------------------------------------------------
// Row-wise LayerNorm. Optional tf32-rounded second output.
// ---------------------------------------------------------------------------
__global__ __launch_bounds__(256)
void ln_kernel(const float* __restrict__ X, const float* __restrict__ g,
               const float* __restrict__ be, float* __restrict__ Y,
               float* __restrict__ Yr)
{
    __shared__ float red[8];
    const int row = blockIdx.x;
    const int tid = threadIdx.x;
    const float* x = X + (size_t)row * DMODEL;

    float v[3];
    float s = 0.f;
    #pragma unroll
    for (int i = 0; i < 3; i++) { v[i] = x[tid + i * 256]; s += v[i]; }

    #pragma unroll
    for (int off = 16; off; off >>= 1) s += __shfl_xor_sync(0xffffffffu, s, off);
    if ((tid & 31) == 0) red[tid >> 5] = s;
    __syncthreads();
    float total = 0.f;
    #pragma unroll
    for (int i = 0; i < 8; i++) total += red[i];
    const float mean = total * (1.0f / DMODEL);
    __syncthreads();

    float s2 = 0.f;
    #pragma unroll
    for (int i = 0; i < 3; i++) { const float d = v[i] - mean; s2 += d * d; }
    #pragma unroll
    for (int off = 16; off; off >>= 1) s2 += __shfl_xor_sync(0xffffffffu, s2, off);
    if ((tid & 31) == 0) red[tid >> 5] = s2;
    __syncthreads();
    float tot2 = 0.f;
    #pragma unroll
    for (int i = 0; i < 8; i++) tot2 += red[i];
    const float rstd = rsqrtf(tot2 * (1.0f / DMODEL) + EPS);

    #pragma unroll
    for (int i = 0; i < 3; i++) {
        const int c = tid + i * 256;
        const float y = (v[i] - mean) * rstd * g[c] + be[c];
        Y[(size_t)row * DMODEL + c] = y;
        if (Yr) Yr[(size_t)row * DMODEL + c] = f2tf32(y);
    }
}

// ---------------------------------------------------------------------------
// Launch
// ---------------------------------------------------------------------------
static void* sym_addr_raw(const void* sym)
{
    void* p = nullptr;
    cudaGetSymbolAddress(&p, sym);
    return p;
}

extern "C" void kernel_launch(void* const* d_in, const int* in_sizes, int n_in,
                              void* d_out, int out_size)
{
    const float* x   = (const float*)d_in[0];
    // d_in[1] = mask (causal; implied)
    const float* wq  = (const float*)d_in[2];
    const float* bq  = (const float*)d_in[3];
    const float* wk  = (const float*)d_in[4];
    const float* bk  = (const float*)d_in[5];
    const float* wv  = (const float*)d_in[6];
    const float* bv  = (const float*)d_in[7];
    const float* wo  = (const float*)d_in[8];
    const float* bo  = (const float*)d_in[9];
    const float* g1  = (const float*)d_in[10];
    const float* be1 = (const float*)d_in[11];
    const float* w1  = (const float*)d_in[12];
    const float* b1  = (const float*)d_in[13];
    const float* w2  = (const float*)d_in[14];
    const float* b2  = (const float*)d_in[15];
    const float* g2  = (const float*)d_in[16];
    const float* be2 = (const float*)d_in[17];
    float* out = (float*)d_out;

    __nv_bfloat16* qb = (__nv_bfloat16*)sym_addr_raw(g_qb);
    __nv_bfloat16* kb = (__nv_bfloat16*)sym_addr_raw(g_kb);
    __nv_bfloat16* vb = (__nv_bfloat16*)sym_addr_raw(g_vb);
    __nv_bfloat16* vT = (__nv_bfloat16*)sym_addr_raw(g_vT);
    __nv_bfloat16* ctxb = (__nv_bfloat16*)sym_addr_raw(g_ctxb);
    float* t1   = (float*)sym_addr_raw(g_t1);
    float* hh   = (float*)sym_addr_raw(g_h);
    float* hr   = (float*)sym_addr_raw(g_hr);
    float* f1   = (float*)sym_addr_raw(g_f1);
    float* t2   = (float*)sym_addr_raw(g_t2);
    __nv_bfloat16* xb    = (__nv_bfloat16*)sym_addr_raw(g_xb);
    __nv_bfloat16* wqkvT = (__nv_bfloat16*)sym_addr_raw(g_wqkvT);
    float*         bqkv  = (float*)sym_addr_raw(g_bqkv);
    __nv_bfloat16* woT   = (__nv_bfloat16*)sym_addr_raw(g_woT);
    float* w1r  = (float*)sym_addr_raw(g_w1r);
    float* w2r  = (float*)sym_addr_raw(g_w2r);

    cudaFuncSetAttribute(attn_bf, cudaFuncAttributeMaxDynamicSharedMemorySize,
                         ATTN_SMEM);
    cudaFuncSetAttribute(gemm_bf<EP_QKV, 128>,
                         cudaFuncAttributeMaxDynamicSharedMemorySize, BF_SMEM_BM(128));
    cudaFuncSetAttribute(gemm_bf<EP_RESID, 64>,
                         cudaFuncAttributeMaxDynamicSharedMemorySize, BF_SMEM_BM(64));
    cudaFuncSetAttribute(gemm_ca<EP_RESID, 64>,
                         cudaFuncAttributeMaxDynamicSharedMemorySize, GEMM_SMEM_BM(64));
    cudaFuncSetAttribute(gemm_ca<EP_GELU_TF32, 64>,
                         cudaFuncAttributeMaxDynamicSharedMemorySize, GEMM_SMEM_BM(64));

    // 0. prep
    const int nX = MROWS * DMODEL / 4;
    const int nW1 = DMODEL * DFF / 4;
    cvt_bf16_kernel<<<(nX + 255)/256, 256>>>(x, xb, nX);
    const dim3 tb(32, 8);
    packT_bf16_kernel<<<dim3(DMODEL/32, DMODEL/32), tb>>>(wq, wqkvT, DMODEL, DMODEL, 0);
    packT_bf16_kernel<<<dim3(DMODEL/32, DMODEL/32), tb>>>(wk, wqkvT, DMODEL, DMODEL, DMODEL);
    packT_bf16_kernel<<<dim3(DMODEL/32, DMODEL/32), tb>>>(wv, wqkvT, DMODEL, DMODEL, 2*DMODEL);
    packT_bf16_kernel<<<dim3(DMODEL/32, DMODEL/32), tb>>>(wo, woT, DMODEL, DMODEL, 0);
    pack_bias_kernel<<<3, 256>>>(bq, bqkv, 0);
    pack_bias_kernel<<<3, 256>>>(bk, bqkv, DMODEL);
    pack_bias_kernel<<<3, 256>>>(bv, bqkv, 2*DMODEL);
    round_tf32_kernel<<<(nW1 + 255)/256, 256>>>(w1, w1r, nW1);
    round_tf32_kernel<<<(nW1 + 255)/256, 256>>>(w2, w2r, nW1);

    // 1. Fused QKV projection (bf16) -> q/k/v bf16 (q pre-scaled 1/8)
    gemm_bf<EP_QKV, 128><<<dim3(NQKV/128, MROWS/128), 256, BF_SMEM_BM(128)>>>(
        xb, wqkvT, bqkv, nullptr, nullptr, NQKV, DMODEL);

    // 1b. transpose V -> vT [b][h*d][s]
    transposeV_kernel<<<dim3(SEQ/32, DMODEL/32, BATCH), dim3(32, 8)>>>(vb, vT);

    // 2. Causal flash attention (bf16 mma, fp32 softmax) -> ctx bf16
    attn_bf<<<dim3(SEQ/128, BATCH*NHEAD), 256, ATTN_SMEM>>>(qb, kb, vT, ctxb);

    // 3. ctx @ wo + bo + x -> t1 (bf16 GEMM, fp32 residual/out)
    gemm_bf<EP_RESID, 64><<<dim3(DMODEL/128, MROWS/64), 256, BF_SMEM_BM(64)>>>(
        ctxb, woT, bo, x, t1, DMODEL, DMODEL);

    // 4. LN1 -> h (fp32) + hr (tf32)
    ln_kernel<<<MROWS, 256>>>(t1, g1, be1, hh, hr);

    // 5. GELU(hr @ w1 + b1) -> f1 (tf32 GEMM)
    gemm_ca<EP_GELU_TF32, 64><<<dim3(DFF/128, MROWS/64), 256, GEMM_SMEM_BM(64)>>>(
        hr, w1r, b1, nullptr, f1, DFF, DMODEL);

    // 6. f1 @ w2 + b2 + h -> t2 (tf32 GEMM)
    gemm_ca<EP_RESID, 64><<<dim3(DMODEL/128, MROWS/64), 256, GEMM_SMEM_BM(64)>>>(
        f1, w2r, b2, hh, t2, DMODEL, DFF);

    // 7. LN2 -> out
    ln_kernel<<<MROWS, 256>>>(t2, g2, be2, out, nullptr);
}

// round 17
// speedup vs baseline: 1.6115x; 1.1245x over previous
#include <cuda_runtime.h>
#include <cuda_bf16.h>
#include <math.h>
#include <stdint.h>

// Problem constants
#define BATCH 4
#define SEQ   2048
#define DMODEL 768
#define NHEAD 12
#define DHEAD 64
#define DFF   3072
#define MROWS (BATCH*SEQ)          // 8192
#define NQKV  (3*DMODEL)           // 2304
#define EPS   1e-5f

// ---------------------------------------------------------------------------
// Scratch (device globals; allocation-free contract)
// ---------------------------------------------------------------------------
__device__ __nv_bfloat16 g_qb [(size_t)MROWS * DMODEL];   // bf16, pre-scaled 1/8
__device__ __nv_bfloat16 g_kb [(size_t)MROWS * DMODEL];
__device__ __nv_bfloat16 g_vT [(size_t)MROWS * DMODEL];   // [b][h*d][s] (written by QKV epi)
__device__ __nv_bfloat16 g_ctxb[(size_t)MROWS * DMODEL];  // attn out (WO A operand)
__device__ float g_t1 [(size_t)MROWS * DMODEL];
__device__ float g_h  [(size_t)MROWS * DMODEL];   // full fp32 (residual)
__device__ __nv_bfloat16 g_hb [(size_t)MROWS * DMODEL];   // FFN1 A operand (bf16)
__device__ float g_f1 [(size_t)MROWS * DFF];      // tf32-rounded fp32 (FFN2 A operand)
__device__ float g_t2 [(size_t)MROWS * DMODEL];
// operands
__device__ __nv_bfloat16 g_xb   [(size_t)MROWS * DMODEL];
__device__ __nv_bfloat16 g_wqkvT[(size_t)NQKV * DMODEL];  // [2304][768] bf16
__device__ float         g_bqkv [NQKV];
__device__ __nv_bfloat16 g_woT  [(size_t)DMODEL * DMODEL];// [768][768] bf16
__device__ __nv_bfloat16 g_w1T  [(size_t)DFF * DMODEL];   // [3072][768] bf16
__device__ float g_w2r [(size_t)DFF * DMODEL];    // tf32

// ---------------------------------------------------------------------------
// helpers
// ---------------------------------------------------------------------------
__device__ __forceinline__ float f2tf32(float x)
{
    uint32_t u;
    asm("cvt.rna.tf32.f32 %0, %1;" : "=r"(u) : "f"(x));
    return __uint_as_float(u);
}

__device__ __forceinline__ void mma_tf32(float* c, const uint32_t* a, const uint32_t* b)
{
    asm volatile(
        "mma.sync.aligned.m16n8k8.row.col.f32.tf32.tf32.f32 "
        "{%0,%1,%2,%3},{%4,%5,%6,%7},{%8,%9},{%0,%1,%2,%3};\n"
        : "+f"(c[0]), "+f"(c[1]), "+f"(c[2]), "+f"(c[3])
        : "r"(a[0]), "r"(a[1]), "r"(a[2]), "r"(a[3]), "r"(b[0]), "r"(b[1]));
}

__device__ __forceinline__ void mma_bf16(float* c, const uint32_t* a, const uint32_t* b)
{
    asm volatile(
        "mma.sync.aligned.m16n8k16.row.col.f32.bf16.bf16.f32 "
        "{%0,%1,%2,%3},{%4,%5,%6,%7},{%8,%9},{%0,%1,%2,%3};\n"
        : "+f"(c[0]), "+f"(c[1]), "+f"(c[2]), "+f"(c[3])
        : "r"(a[0]), "r"(a[1]), "r"(a[2]), "r"(a[3]), "r"(b[0]), "r"(b[1]));
}

__device__ __forceinline__ uint32_t smem_u32(const void* p)
{
    return (uint32_t)__cvta_generic_to_shared(p);
}

#define CPA16(dst, src) \
    asm volatile("cp.async.cg.shared.global [%0], [%1], 16;\n" :: "r"(dst), "l"(src))
#define CPA_COMMIT() asm volatile("cp.async.commit_group;\n")
#define CPA_WAIT1()  asm volatile("cp.async.wait_group 1;\n")
#define CPA_WAIT0()  asm volatile("cp.async.wait_group 0;\n")

// ---------------------------------------------------------------------------
// Prep kernels
// ---------------------------------------------------------------------------
__global__ __launch_bounds__(256)
void round_tf32_kernel(const float* __restrict__ src, float* __restrict__ dst, int n4)
{
    const int i = blockIdx.x * blockDim.x + threadIdx.x;
    if (i < n4) {
        float4 v = *((const float4*)src + i);
        v.x = f2tf32(v.x); v.y = f2tf32(v.y);
        v.z = f2tf32(v.z); v.w = f2tf32(v.w);
        *((float4*)dst + i) = v;
    }
}

__global__ __launch_bounds__(256)
void cvt_bf16_kernel(const float* __restrict__ src, __nv_bfloat16* __restrict__ dst, int n4)
{
    const int i = blockIdx.x * blockDim.x + threadIdx.x;
    if (i < n4) {
        float4 v = *((const float4*)src + i);
        *(__nv_bfloat162*)(dst + (size_t)i*4)     = __floats2bfloat162_rn(v.x, v.y);
        *(__nv_bfloat162*)(dst + (size_t)i*4 + 2) = __floats2bfloat162_rn(v.z, v.w);
    }
}

// src [K][N] fp32 -> dst rows (off+n) of [*][K] bf16 (transpose + convert)
__global__ __launch_bounds__(256)
void packT_bf16_kernel(const float* __restrict__ src, __nv_bfloat16* __restrict__ dst,
                       int K, int N, int off)
{
    __shared__ float t[32][33];
    const int k0 = blockIdx.x * 32;
    const int n0 = blockIdx.y * 32;
    const int x = threadIdx.x;
    const int y = threadIdx.y;
    #pragma unroll
    for (int i = 0; i < 32; i += 8)
        t[y + i][x] = src[(size_t)(k0 + y + i) * N + n0 + x];
    __syncthreads();
    #pragma unroll
    for (int i = 0; i < 32; i += 8)
        dst[(size_t)(off + n0 + y + i) * K + k0 + x] = __float2bfloat16_rn(t[x][y + i]);
}

__global__ __launch_bounds__(256)
void pack_bias_kernel(const float* __restrict__ src, float* __restrict__ dst, int off)
{
    const int i = blockIdx.x * blockDim.x + threadIdx.x;
    if (i < DMODEL) dst[off + i] = src[i];
}

enum { EP_RESID = 1, EP_GELU_TF32 = 2, EP_QKV = 4 };

// ---------------------------------------------------------------------------
// tf32 cp.async GEMM (verified R11): C = A[M,K] @ B[K,N] + bias (+epilogue).
// BM=64; BN=128, BK=16, 256 threads, warp tile 32x32.
// ---------------------------------------------------------------------------
#define APITCH 20
#define BPITCH 136
#define BBUF   (16*BPITCH)
#define GEMM_SMEM_BM(BM) ((3*((BM)*APITCH) + 3*BBUF) * 4)

template<int EPI, int BM>
__global__ __launch_bounds__(256)
void gemm_ca(const float* __restrict__ A, const float* __restrict__ Bm,
             const float* __restrict__ bias, const float* __restrict__ resid,
             float* __restrict__ C, int Ndim, int Kdim)
{
    constexpr int WROWS = BM / 2;
    constexpr int MT    = WROWS / 16;
    constexpr int ABUFT = BM * APITCH;

    extern __shared__ float gsm[];
    float* As = gsm;
    float* Bs = gsm + 3*ABUFT;

    const int tid  = threadIdx.x;
    const int lane = tid & 31;
    const int warp = tid >> 5;
    const int wm = warp & 1;
    const int wn = warp >> 1;
    const int g = lane >> 2;
    const int q = lane & 3;
    const int row0 = blockIdx.y * BM;
    const int col0 = blockIdx.x * 128;

    const int br = tid >> 4;
    const int bc8 = (tid & 15) * 8;

    const uint32_t asu = smem_u32(As);
    const uint32_t bsu = smem_u32(Bs);

    float acc[MT][4][4];
    #pragma unroll
    for (int i = 0; i < MT; i++)
        #pragma unroll
        for (int j = 0; j < 4; j++)
            #pragma unroll
            for (int r = 0; r < 4; r++) acc[i][j][r] = 0.f;

    const int nk = Kdim >> 4;

    #define GISSUE(i, bf_) do {                                                     \
        const int k0_ = (i) << 4;                                                   \
        if (BM == 128) {                                                            \
            const int ar  = tid >> 1;                                               \
            const int ac8 = (tid & 1) * 8;                                          \
            const float* asrc = A + (size_t)(row0 + ar) * Kdim + k0_ + ac8;         \
            const uint32_t ad = asu + (uint32_t)((bf_)*ABUFT + ar*APITCH + ac8)*4u; \
            CPA16(ad,       asrc);                                                  \
            CPA16(ad + 16u, asrc + 4);                                              \
        } else {                                                                    \
            const int ar  = tid >> 2;                                               \
            const int ac4 = (tid & 3) * 4;                                          \
            const float* asrc = A + (size_t)(row0 + ar) * Kdim + k0_ + ac4;         \
            const uint32_t ad = asu + (uint32_t)((bf_)*ABUFT + ar*APITCH + ac4)*4u; \
            CPA16(ad, asrc);                                                        \
        }                                                                           \
        const float* bsrc = Bm + (size_t)(k0_ + br) * Ndim + col0 + bc8;            \
        const uint32_t bd = bsu + (uint32_t)((bf_)*BBUF + br*BPITCH + bc8) * 4u;    \
        CPA16(bd,       bsrc);                                                      \
        CPA16(bd + 16u, bsrc + 4);                                                  \
        CPA_COMMIT();                                                               \
    } while (0)

    #define GCOMPUTE(bf_) do {                                                    \
        const float* Ab = As + (bf_)*ABUFT;                                       \
        const float* Bb = Bs + (bf_)*BBUF;                                        \
        _Pragma("unroll")                                                         \
        for (int ks = 0; ks < 16; ks += 8) {                                      \
            uint32_t af[MT][4], bf2[4][2];                                        \
            _Pragma("unroll")                                                     \
            for (int mt = 0; mt < MT; mt++) {                                     \
                const int m0 = wm*WROWS + mt*16;                                  \
                af[mt][0] = __float_as_uint(Ab[(m0+g  )*APITCH + ks+q  ]);        \
                af[mt][1] = __float_as_uint(Ab[(m0+g+8)*APITCH + ks+q  ]);        \
                af[mt][2] = __float_as_uint(Ab[(m0+g  )*APITCH + ks+q+4]);        \
                af[mt][3] = __float_as_uint(Ab[(m0+g+8)*APITCH + ks+q+4]);        \
            }                                                                     \
            _Pragma("unroll")                                                     \
            for (int nt = 0; nt < 4; nt++) {                                      \
                const int n0 = wn*32 + nt*8;                                      \
                bf2[nt][0] = __float_as_uint(Bb[(ks+q  )*BPITCH + n0+g]);         \
                bf2[nt][1] = __float_as_uint(Bb[(ks+q+4)*BPITCH + n0+g]);         \
            }                                                                     \
            _Pragma("unroll")                                                     \
            for (int mt = 0; mt < MT; mt++)                                       \
                _Pragma("unroll")                                                 \
                for (int nt = 0; nt < 4; nt++)                                    \
                    mma_tf32(acc[mt][nt], af[mt], bf2[nt]);                       \
        }                                                                         \
    } while (0)

    GISSUE(0, 0);
    GISSUE(1, 1);

    for (int i = 0; i < nk; i++) {
        if (i + 1 < nk) { CPA_WAIT1(); } else { CPA_WAIT0(); }
        __syncthreads();
        const int cb = i % 3;
        GCOMPUTE(cb);
        if (i + 2 < nk) GISSUE(i + 2, (i + 2) % 3);
        __syncthreads();
    }

    #undef GISSUE
    #undef GCOMPUTE

    #pragma unroll
    for (int mt = 0; mt < MT; mt++) {
        const int mlo = row0 + wm*WROWS + mt*16 + g;
        #pragma unroll
        for (int nt = 0; nt < 4; nt++) {
            const int n = col0 + wn*32 + nt*8 + 2*q;
            const float b0 = bias[n], b1 = bias[n+1];
            #pragma unroll
            for (int half = 0; half < 2; half++) {
                const int m = mlo + half*8;
                float v0 = acc[mt][nt][half*2+0] + b0;
                float v1 = acc[mt][nt][half*2+1] + b1;
                if (EPI == EP_RESID) {
                    v0 += resid[(size_t)m * Ndim + n];
                    v1 += resid[(size_t)m * Ndim + n + 1];
                    *(float2*)(C + (size_t)m * Ndim + n) = make_float2(v0, v1);
                }
            }
        }
    }
}

// ---------------------------------------------------------------------------
// bf16 cp.async GEMM (validated R12/R13/R15).
// BM in {128,64}, BN=128, BK=32, 256 threads, warp tile (BM/2)x32.
// EP_QKV: scatter bf16 q/k + V directly transposed to g_vT.
// EP_RESID: fp32 out + fp32 residual.
// EP_GELU_TF32: GELU, tf32-round, fp32 out (FFN2 tf32 A operand).
// ---------------------------------------------------------------------------
#define KP 40
#define BF_SMEM_BM(BM) ((3*((BM)*KP) + 3*(128*KP)) * 2)

template<int EPI, int BM>
__global__ __launch_bounds__(256)
void gemm_bf(const __nv_bfloat16* __restrict__ A, const __nv_bfloat16* __restrict__ BT,
             const float* __restrict__ bias, const float* __restrict__ resid,
             float* __restrict__ Cf, int Ndim, int Kdim)
{
    constexpr int WROWS = BM / 2;
    constexpr int MT    = WROWS / 16;
    constexpr int ABUFT = BM * KP;
    constexpr int BBUFT = 128 * KP;

    extern __shared__ __align__(16) char gsmraw[];
    __nv_bfloat16* As = (__nv_bfloat16*)gsmraw;
    __nv_bfloat16* Bs = As + 3*ABUFT;

    const int tid  = threadIdx.x;
    const int lane = tid & 31;
    const int warp = tid >> 5;
    const int wm = warp & 1;
    const int wn = warp >> 1;
    const int g = lane >> 2;
    const int q = lane & 3;
    const int row0 = blockIdx.y * BM;
    const int col0 = blockIdx.x * 128;

    const uint32_t asu = smem_u32(As);
    const uint32_t bsu = smem_u32(Bs);

    float acc[MT][4][4];
    #pragma unroll
    for (int i = 0; i < MT; i++)
        #pragma unroll
        for (int j = 0; j < 4; j++)
            #pragma unroll
            for (int r = 0; r < 4; r++) acc[i][j][r] = 0.f;

    const int nk = Kdim >> 5;

    #define GISSUE(i, bf_) do {                                                       \
        const int k0_ = (i) << 5;                                                     \
        if (BM == 128) {                                                              \
            const int ar = tid >> 1;                                                  \
            const int ac = (tid & 1) * 16;                                            \
            const __nv_bfloat16* asrc = A + (size_t)(row0 + ar) * Kdim + k0_ + ac;    \
            const uint32_t ad = asu + (uint32_t)((bf_)*ABUFT + ar*KP + ac) * 2u;      \
            CPA16(ad,       asrc);                                                    \
            CPA16(ad + 16u, asrc + 8);                                                \
        } else {                                                                      \
            const int ar = tid >> 2;                                                  \
            const int ac = (tid & 3) * 8;                                             \
            const __nv_bfloat16* asrc = A + (size_t)(row0 + ar) * Kdim + k0_ + ac;    \
            const uint32_t ad = asu + (uint32_t)((bf_)*ABUFT + ar*KP + ac) * 2u;      \
            CPA16(ad, asrc);                                                          \
        }                                                                             \
        {                                                                             \
            const int br = tid >> 1;                                                  \
            const int bc = (tid & 1) * 16;                                            \
            const __nv_bfloat16* bsrc = BT + (size_t)(col0 + br) * Kdim + k0_ + bc;   \
            const uint32_t bd = bsu + (uint32_t)((bf_)*BBUFT + br*KP + bc) * 2u;      \
            CPA16(bd,       bsrc);                                                    \
            CPA16(bd + 16u, bsrc + 8);                                                \
        }                                                                             \
        CPA_COMMIT();                                                                 \
    } while (0)

    #define GCOMPUTE(bf_) do {                                                        \
        const __nv_bfloat16* Ab = As + (bf_)*ABUFT;                                   \
        const __nv_bfloat16* Bb = Bs + (bf_)*BBUFT;                                   \
        _Pragma("unroll")                                                             \
        for (int ks = 0; ks < 32; ks += 16) {                                         \
            uint32_t af[MT][4], bf2[4][2];                                            \
            _Pragma("unroll")                                                         \
            for (int mt = 0; mt < MT; mt++) {                                         \
                const int m0 = wm*WROWS + mt*16;                                      \
                af[mt][0] = *(const uint32_t*)&Ab[(m0+g  )*KP + ks + 2*q    ];        \
                af[mt][1] = *(const uint32_t*)&Ab[(m0+g+8)*KP + ks + 2*q    ];        \
                af[mt][2] = *(const uint32_t*)&Ab[(m0+g  )*KP + ks + 2*q + 8];        \
                af[mt][3] = *(const uint32_t*)&Ab[(m0+g+8)*KP + ks + 2*q + 8];        \
            }                                                                         \
            _Pragma("unroll")                                                         \
            for (int nt = 0; nt < 4; nt++) {                                          \
                const int n0 = wn*32 + nt*8;                                          \
                bf2[nt][0] = *(const uint32_t*)&Bb[(n0+g)*KP + ks + 2*q    ];         \
                bf2[nt][1] = *(const uint32_t*)&Bb[(n0+g)*KP + ks + 2*q + 8];         \
            }                                                                         \
            _Pragma("unroll")                                                         \
            for (int mt = 0; mt < MT; mt++)                                           \
                _Pragma("unroll")                                                     \
                for (int nt = 0; nt < 4; nt++)                                        \
                    mma_bf16(acc[mt][nt], af[mt], bf2[nt]);                           \
        }                                                                             \
    } while (0)

    GISSUE(0, 0);
    GISSUE(1, 1);

    for (int i = 0; i < nk; i++) {
        if (i + 1 < nk) { CPA_WAIT1(); } else { CPA_WAIT0(); }
        __syncthreads();
        const int cb = i % 3;
        GCOMPUTE(cb);
        if (i + 2 < nk) GISSUE(i + 2, (i + 2) % 3);
        __syncthreads();
    }

    #undef GISSUE
    #undef GCOMPUTE

    #pragma unroll
    for (int mt = 0; mt < MT; mt++) {
        const int mlo = row0 + wm*WROWS + mt*16 + g;
        #pragma unroll
        for (int nt = 0; nt < 4; nt++) {
            const int n = col0 + wn*32 + nt*8 + 2*q;
            const float b0 = bias[n], b1 = bias[n+1];
            #pragma unroll
            for (int half = 0; half < 2; half++) {
                const int m = mlo + half*8;
                float v0 = acc[mt][nt][half*2+0] + b0;
                float v1 = acc[mt][nt][half*2+1] + b1;
                if (EPI == EP_RESID) {
                    v0 += resid[(size_t)m * Ndim + n];
                    v1 += resid[(size_t)m * Ndim + n + 1];
                    *(float2*)(Cf + (size_t)m * Ndim + n) = make_float2(v0, v1);
                }
                if (EPI == EP_GELU_TF32) {
                    v0 = f2tf32(0.5f * v0 * (1.0f + erff(v0 * 0.70710678118654752f)));
                    v1 = f2tf32(0.5f * v1 * (1.0f + erff(v1 * 0.70710678118654752f)));
                    *(float2*)(Cf + (size_t)m * Ndim + n) = make_float2(v0, v1);
                }
                if (EPI == EP_QKV) {
                    if (n < DMODEL) {
                        *(__nv_bfloat162*)(g_qb + (size_t)m * DMODEL + n) =
                            __floats2bfloat162_rn(v0 * 0.125f, v1 * 0.125f);
                    } else if (n < 2*DMODEL) {
                        *(__nv_bfloat162*)(g_kb + (size_t)m * DMODEL + n - DMODEL) =
                            __floats2bfloat162_rn(v0, v1);
                    } else {
                        // write V directly transposed: vT[b][nc][s]
                        const int nc = n - 2*DMODEL;
                        const int bb_ = m >> 11;            // m / SEQ
                        const int ss  = m & (SEQ - 1);
                        g_vT[((size_t)(bb_*DMODEL + nc    ))*SEQ + ss] = __float2bfloat16_rn(v0);
                        g_vT[((size_t)(bb_*DMODEL + nc + 1))*SEQ + ss] = __float2bfloat16_rn(v1);
                    }
                }
            }
        }
    }
}

// ---------------------------------------------------------------------------
// Tensor-core flash attention (causal, bf16 mma, fp32 softmax). Verified R14/R15.
// ---------------------------------------------------------------------------
#define AP 72
#define ATTN_SMEM ((2*64*AP + 2*64*AP + 128*AP) * 2)   // 55296 B

__global__ __launch_bounds__(256, 2)
void attn_bf(const __nv_bfloat16* __restrict__ Q, const __nv_bfloat16* __restrict__ K,
             const __nv_bfloat16* __restrict__ Vt, __nv_bfloat16* __restrict__ ctx)
{
    extern __shared__ __align__(16) char smraw[];
    __nv_bfloat16* sm = (__nv_bfloat16*)smraw;
    __nv_bfloat16* Kb[2] = { sm,            sm + 64*AP };
    __nv_bfloat16* Vb[2] = { sm + 2*64*AP,  sm + 3*64*AP };
    __nv_bfloat16* Ps    = sm + 4*64*AP;

    const int bh = blockIdx.y;
    const int b  = bh / NHEAD;
    const int h  = bh % NHEAD;
    const int qt = (SEQ/128 - 1) - blockIdx.x;
    const int tid  = threadIdx.x;
    const int warp = tid >> 5;
    const int lane = tid & 31;
    const int g = lane >> 2;
    const int q = lane & 3;
    const int wrow = warp * 16;
    const int qbase = qt * 128;

    const int lr = tid >> 2;
    const int cb = (tid & 3) * 16;

    const uint32_t kbu[2] = { smem_u32(Kb[0]), smem_u32(Kb[1]) };
    const uint32_t vbu[2] = { smem_u32(Vb[0]), smem_u32(Vb[1]) };

    #define ISSUE_TILE(kb, sel) do {                                                        \
        const __nv_bfloat16* ksrc =                                                         \
            K  + ((size_t)(b*SEQ + (kb)*64 + lr))*DMODEL + h*DHEAD + cb;                    \
        const __nv_bfloat16* vsrc =                                                         \
            Vt + ((size_t)(b*DMODEL + h*DHEAD + lr))*SEQ + (kb)*64 + cb;                    \
        const uint32_t kd = kbu[sel] + (uint32_t)(lr*AP + cb) * 2u;                         \
        const uint32_t vd = vbu[sel] + (uint32_t)(lr*AP + cb) * 2u;                         \
        CPA16(kd,       ksrc);                                                              \
        CPA16(kd + 16u, ksrc + 8);                                                          \
        CPA16(vd,       vsrc);                                                              \
        CPA16(vd + 16u, vsrc + 8);                                                          \
        CPA_COMMIT();                                                                       \
    } while (0)

    ISSUE_TILE(0, 0);

    {
        const int qlr = tid >> 1;
        const int qlc = (tid & 1) * 32;
        const __nv_bfloat16* qsrc =
            Q + ((size_t)(b*SEQ + qbase + qlr))*DMODEL + h*DHEAD + qlc;
        #pragma unroll
        for (int i = 0; i < 4; i++)
            *(uint4*)&Ps[qlr*AP + qlc + i*8] = *(const uint4*)(qsrc + i*8);
    }
    __syncthreads();
    uint32_t qf[4][4];
    #pragma unroll
    for (int ks = 0; ks < 4; ks++) {
        qf[ks][0] = *(const uint32_t*)&Ps[(wrow+g  )*AP + ks*16 + 2*q    ];
        qf[ks][1] = *(const uint32_t*)&Ps[(wrow+g+8)*AP + ks*16 + 2*q    ];
        qf[ks][2] = *(const uint32_t*)&Ps[(wrow+g  )*AP + ks*16 + 2*q + 8];
        qf[ks][3] = *(const uint32_t*)&Ps[(wrow+g+8)*AP + ks*16 + 2*q + 8];
    }
    __syncthreads();

    float oacc[8][4];
    #pragma unroll
    for (int nt = 0; nt < 8; nt++)
        #pragma unroll
        for (int e = 0; e < 4; e++) oacc[nt][e] = 0.f;
    float m0 = -1e30f, m1 = -1e30f, l0 = 0.f, l1 = 0.f;

    const int nkb = 2*qt + 2;

    for (int kb = 0; kb < nkb; kb++) {
        const int cur = kb & 1;
        if (kb + 1 < nkb) {
            ISSUE_TILE(kb + 1, cur ^ 1);
            CPA_WAIT1();
        } else {
            CPA_WAIT0();
        }
        __syncthreads();

        const bool skip = (kb*64) > (qbase + wrow + 15);
        if (!skip) {
            const __nv_bfloat16* Ksm = Kb[cur];
            const __nv_bfloat16* Vsm = Vb[cur];

            float sacc[8][4];
            #pragma unroll
            for (int nt = 0; nt < 8; nt++)
                #pragma unroll
                for (int e = 0; e < 4; e++) sacc[nt][e] = 0.f;

            #pragma unroll
            for (int ks = 0; ks < 4; ks++) {
                #pragma unroll
                for (int nt = 0; nt < 8; nt++) {
                    uint32_t bb[2];
                    bb[0] = *(const uint32_t*)&Ksm[(nt*8+g)*AP + ks*16 + 2*q    ];
                    bb[1] = *(const uint32_t*)&Ksm[(nt*8+g)*AP + ks*16 + 2*q + 8];
                    mma_bf16(sacc[nt], qf[ks], bb);
                }
            }

            if (kb*64 + 63 > qbase + wrow) {
                const int r0 = qbase + wrow + g;
                const int r1 = r0 + 8;
                #pragma unroll
                for (int nt = 0; nt < 8; nt++) {
                    const int colg = kb*64 + nt*8 + 2*q;
                    if (colg     > r0) sacc[nt][0] = -1e30f;
                    if (colg + 1 > r0) sacc[nt][1] = -1e30f;
                    if (colg     > r1) sacc[nt][2] = -1e30f;
                    if (colg + 1 > r1) sacc[nt][3] = -1e30f;
                }
            }

            float rm0 = -1e30f, rm1 = -1e30f;
            #pragma unroll
            for (int nt = 0; nt < 8; nt++) {
                rm0 = fmaxf(rm0, fmaxf(sacc[nt][0], sacc[nt][1]));
                rm1 = fmaxf(rm1, fmaxf(sacc[nt][2], sacc[nt][3]));
            }
            rm0 = fmaxf(rm0, __shfl_xor_sync(0xffffffffu, rm0, 1));
            rm0 = fmaxf(rm0, __shfl_xor_sync(0xffffffffu, rm0, 2));
            rm1 = fmaxf(rm1, __shfl_xor_sync(0xffffffffu, rm1, 1));
            rm1 = fmaxf(rm1, __shfl_xor_sync(0xffffffffu, rm1, 2));

            const float mn0 = fmaxf(m0, rm0);
            const float mn1 = fmaxf(m1, rm1);
            const float c0 = __expf(m0 - mn0);
            const float c1 = __expf(m1 - mn1);
            m0 = mn0; m1 = mn1;

            float s0 = 0.f, s1 = 0.f;
            #pragma unroll
            for (int nt = 0; nt < 8; nt++) {
                float p;
                p = __expf(sacc[nt][0] - mn0); s0 += p; sacc[nt][0] = p;
                p = __expf(sacc[nt][1] - mn0); s0 += p; sacc[nt][1] = p;
                p = __expf(sacc[nt][2] - mn1); s1 += p; sacc[nt][2] = p;
                p = __expf(sacc[nt][3] - mn1); s1 += p; sacc[nt][3] = p;
            }
            s0 += __shfl_xor_sync(0xffffffffu, s0, 1);
            s0 += __shfl_xor_sync(0xffffffffu, s0, 2);
            s1 += __shfl_xor_sync(0xffffffffu, s1, 1);
            s1 += __shfl_xor_sync(0xffffffffu, s1, 2);
            l0 = l0 * c0 + s0;
            l1 = l1 * c1 + s1;

            #pragma unroll
            for (int nt = 0; nt < 8; nt++) {
                oacc[nt][0] *= c0; oacc[nt][1] *= c0;
                oacc[nt][2] *= c1; oacc[nt][3] *= c1;
            }

            #pragma unroll
            for (int nt = 0; nt < 8; nt++) {
                *(__nv_bfloat162*)&Ps[(wrow+g  )*AP + nt*8 + 2*q] =
                    __floats2bfloat162_rn(sacc[nt][0], sacc[nt][1]);
                *(__nv_bfloat162*)&Ps[(wrow+g+8)*AP + nt*8 + 2*q] =
                    __floats2bfloat162_rn(sacc[nt][2], sacc[nt][3]);
            }
            __syncwarp();

            #pragma unroll
            for (int ks = 0; ks < 4; ks++) {
                uint32_t a[4];
                a[0] = *(const uint32_t*)&Ps[(wrow+g  )*AP + ks*16 + 2*q    ];
                a[1] = *(const uint32_t*)&Ps[(wrow+g+8)*AP + ks*16 + 2*q    ];
                a[2] = *(const uint32_t*)&Ps[(wrow+g  )*AP + ks*16 + 2*q + 8];
                a[3] = *(const uint32_t*)&Ps[(wrow+g+8)*AP + ks*16 + 2*q + 8];
                #pragma unroll
                for (int nt = 0; nt < 8; nt++) {
                    uint32_t bb[2];
                    bb[0] = *(const uint32_t*)&Vsm[(nt*8+g)*AP + ks*16 + 2*q    ];
                    bb[1] = *(const uint32_t*)&Vsm[(nt*8+g)*AP + ks*16 + 2*q + 8];
                    mma_bf16(oacc[nt], a, bb);
                }
            }
        }
        __syncthreads();
    }
    #undef ISSUE_TILE

    const float i0 = 1.f / l0;
    const float i1 = 1.f / l1;
    __nv_bfloat16* c0p = ctx + ((size_t)(b*SEQ + qbase + wrow + g    )) * DMODEL + h*DHEAD;
    __nv_bfloat16* c1p = ctx + ((size_t)(b*SEQ + qbase + wrow + g + 8)) * DMODEL + h*DHEAD;
    #pragma unroll
    for (int nt = 0; nt < 8; nt++) {
        *(__nv_bfloat162*)(c0p + nt*8 + 2*q) =
            __floats2bfloat162_rn(oacc[nt][0]*i0, oacc[nt][1]*i0);
        *(__nv_bfloat162*)(c1p + nt*8 + 2*q) =
            __floats2bfloat162_rn(oacc[nt][2]*i1, oacc[nt][3]*i1);
    }
}

// ---------------------------------------------------------------------------
// Row-wise LayerNorm. Optional bf16 second output (FFN1 A operand).
// ---------------------------------------------------------------------------
__global__ __launch_bounds__(256)
void ln_kernel(const float* __restrict__ X, const float* __restrict__ g,
               const float* __restrict__ be, float* __restrict__ Y,
               __nv_bfloat16* __restrict__ Yb)
{
    __shared__ float red[8];
    const int row = blockIdx.x;
    const int tid = threadIdx.x;
    const float* x = X + (size_t)row * DMODEL;

    float v[3];
    float s = 0.f;
    #pragma unroll
    for (int i = 0; i < 3; i++) { v[i] = x[tid + i * 256]; s += v[i]; }

    #pragma unroll
    for (int off = 16; off; off >>= 1) s += __shfl_xor_sync(0xffffffffu, s, off);
    if ((tid & 31) == 0) red[tid >> 5] = s;
    __syncthreads();
    float total = 0.f;
    #pragma unroll
    for (int i = 0; i < 8; i++) total += red[i];
    const float mean = total * (1.0f / DMODEL);
    __syncthreads();

    float s2 = 0.f;
    #pragma unroll
    for (int i = 0; i < 3; i++) { const float d = v[i] - mean; s2 += d * d; }
    #pragma unroll
    for (int off = 16; off; off >>= 1) s2 += __shfl_xor_sync(0xffffffffu, s2, off);
    if ((tid & 31) == 0) red[tid >> 5] = s2;
    __syncthreads();
    float tot2 = 0.f;
    #pragma unroll
    for (int i = 0; i < 8; i++) tot2 += red[i];
    const float rstd = rsqrtf(tot2 * (1.0f / DMODEL) + EPS);

    #pragma unroll
    for (int i = 0; i < 3; i++) {
        const int c = tid + i * 256;
        const float y = (v[i] - mean) * rstd * g[c] + be[c];
        Y[(size_t)row * DMODEL + c] = y;
        if (Yb) Yb[(size_t)row * DMODEL + c] = __float2bfloat16_rn(y);
    }
}

// ---------------------------------------------------------------------------
// Launch
// ---------------------------------------------------------------------------
static void* sym_addr_raw(const void* sym)
{
    void* p = nullptr;
    cudaGetSymbolAddress(&p, sym);
    return p;
}

extern "C" void kernel_launch(void* const* d_in, const int* in_sizes, int n_in,
                              void* d_out, int out_size)
{
    const float* x   = (const float*)d_in[0];
    // d_in[1] = mask (causal; implied)
    const float* wq  = (const float*)d_in[2];
    const float* bq  = (const float*)d_in[3];
    const float* wk  = (const float*)d_in[4];
    const float* bk  = (const float*)d_in[5];
    const float* wv  = (const float*)d_in[6];
    const float* bv  = (const float*)d_in[7];
    const float* wo  = (const float*)d_in[8];
    const float* bo  = (const float*)d_in[9];
    const float* g1  = (const float*)d_in[10];
    const float* be1 = (const float*)d_in[11];
    const float* w1  = (const float*)d_in[12];
    const float* b1  = (const float*)d_in[13];
    const float* w2  = (const float*)d_in[14];
    const float* b2  = (const float*)d_in[15];
    const float* g2  = (const float*)d_in[16];
    const float* be2 = (const float*)d_in[17];
    float* out = (float*)d_out;

    __nv_bfloat16* qb = (__nv_bfloat16*)sym_addr_raw(g_qb);
    __nv_bfloat16* kb = (__nv_bfloat16*)sym_addr_raw(g_kb);
    __nv_bfloat16* vT = (__nv_bfloat16*)sym_addr_raw(g_vT);
    __nv_bfloat16* ctxb = (__nv_bfloat16*)sym_addr_raw(g_ctxb);
    float* t1   = (float*)sym_addr_raw(g_t1);
    float* hh   = (float*)sym_addr_raw(g_h);
    __nv_bfloat16* hb = (__nv_bfloat16*)sym_addr_raw(g_hb);
    float* f1   = (float*)sym_addr_raw(g_f1);
    float* t2   = (float*)sym_addr_raw(g_t2);
    __nv_bfloat16* xb    = (__nv_bfloat16*)sym_addr_raw(g_xb);
    __nv_bfloat16* wqkvT = (__nv_bfloat16*)sym_addr_raw(g_wqkvT);
    float*         bqkv  = (float*)sym_addr_raw(g_bqkv);
    __nv_bfloat16* woT   = (__nv_bfloat16*)sym_addr_raw(g_woT);
    __nv_bfloat16* w1T   = (__nv_bfloat16*)sym_addr_raw(g_w1T);
    float* w2r  = (float*)sym_addr_raw(g_w2r);

    cudaFuncSetAttribute(attn_bf, cudaFuncAttributeMaxDynamicSharedMemorySize,
                         ATTN_SMEM);
    cudaFuncSetAttribute(gemm_bf<EP_QKV, 128>,
                         cudaFuncAttributeMaxDynamicSharedMemorySize, BF_SMEM_BM(128));
    cudaFuncSetAttribute(gemm_bf<EP_RESID, 64>,
                         cudaFuncAttributeMaxDynamicSharedMemorySize, BF_SMEM_BM(64));
    cudaFuncSetAttribute(gemm_bf<EP_GELU_TF32, 64>,
                         cudaFuncAttributeMaxDynamicSharedMemorySize, BF_SMEM_BM(64));
    cudaFuncSetAttribute(gemm_ca<EP_RESID, 64>,
                         cudaFuncAttributeMaxDynamicSharedMemorySize, GEMM_SMEM_BM(64));

    // 0. prep
    const int nX = MROWS * DMODEL / 4;
    const int nW1 = DMODEL * DFF / 4;
    cvt_bf16_kernel<<<(nX + 255)/256, 256>>>(x, xb, nX);
    const dim3 tb(32, 8);
    packT_bf16_kernel<<<dim3(DMODEL/32, DMODEL/32), tb>>>(wq, wqkvT, DMODEL, DMODEL, 0);
    packT_bf16_kernel<<<dim3(DMODEL/32, DMODEL/32), tb>>>(wk, wqkvT, DMODEL, DMODEL, DMODEL);
    packT_bf16_kernel<<<dim3(DMODEL/32, DMODEL/32), tb>>>(wv, wqkvT, DMODEL, DMODEL, 2*DMODEL);
    packT_bf16_kernel<<<dim3(DMODEL/32, DMODEL/32), tb>>>(wo, woT, DMODEL, DMODEL, 0);
    packT_bf16_kernel<<<dim3(DMODEL/32, DFF/32),    tb>>>(w1, w1T, DMODEL, DFF, 0);
    pack_bias_kernel<<<3, 256>>>(bq, bqkv, 0);
    pack_bias_kernel<<<3, 256>>>(bk, bqkv, DMODEL);
    pack_bias_kernel<<<3, 256>>>(bv, bqkv, 2*DMODEL);
    round_tf32_kernel<<<(nW1 + 255)/256, 256>>>(w2, w2r, nW1);

    // 1. Fused QKV projection (bf16) -> q/k bf16 + V transposed bf16
    gemm_bf<EP_QKV, 128><<<dim3(NQKV/128, MROWS/128), 256, BF_SMEM_BM(128)>>>(
        xb, wqkvT, bqkv, nullptr, nullptr, NQKV, DMODEL);

    // 2. Causal flash attention (bf16 mma, fp32 softmax) -> ctx bf16
    attn_bf<<<dim3(SEQ/128, BATCH*NHEAD), 256, ATTN_SMEM>>>(qb, kb, vT, ctxb);

    // 3. ctx @ wo + bo + x -> t1 (bf16 GEMM, fp32 residual/out)
    gemm_bf<EP_RESID, 64><<<dim3(DMODEL/128, MROWS/64), 256, BF_SMEM_BM(64)>>>(
        ctxb, woT, bo, x, t1, DMODEL, DMODEL);

    // 4. LN1 -> h (fp32) + hb (bf16)
    ln_kernel<<<MROWS, 256>>>(t1, g1, be1, hh, hb);

    // 5. GELU(hb @ w1 + b1) -> f1 (bf16 GEMM, tf32-rounded fp32 out)
    gemm_bf<EP_GELU_TF32, 64><<<dim3(DFF/128, MROWS/64), 256, BF_SMEM_BM(64)>>>(
        hb, w1T, b1, nullptr, f1, DFF, DMODEL);

    // 6. f1 @ w2 + b2 + h -> t2 (tf32 GEMM)
    gemm_ca<EP_RESID, 64><<<dim3(DMODEL/128, MROWS/64), 256, GEMM_SMEM_BM(64)>>>(
        f1, w2r, b2, hh, t2, DMODEL, DFF);

    // 7. LN2 -> out
    ln_kernel<<<MROWS, 256>>>(t2, g2, be2, out, nullptr);
}